// round 14
// baseline (speedup 1.0000x reference)
#include <cuda_runtime.h>
#include <cuda_bf16.h>
#include <math.h>

#define N_MAX 10000
#define E_MAX 160000
#define NW 8
#define RC_F 4.5f
#define PI_F 3.14159265358979323846f

typedef unsigned long long ull;

__device__ __forceinline__ ull fma2(ull a, ull b, ull c) {
    ull d; asm("fma.rn.f32x2 %0,%1,%2,%3;" : "=l"(d) : "l"(a), "l"(b), "l"(c)); return d;
}
__device__ __forceinline__ ull mul2(ull a, ull b) {
    ull d; asm("mul.rn.f32x2 %0,%1,%2;" : "=l"(d) : "l"(a), "l"(b)); return d;
}
__device__ __forceinline__ ull add2(ull a, ull b) {
    ull d; asm("add.rn.f32x2 %0,%1,%2;" : "=l"(d) : "l"(a), "l"(b)); return d;
}
__device__ __forceinline__ ull packdup(float x) {
    ull d; asm("mov.b64 %0,{%1,%1};" : "=l"(d) : "f"(x)); return d;
}
__device__ __forceinline__ unsigned packbf(float a, float b) {
    __nv_bfloat16 ba = __float2bfloat16_rn(a), bb = __float2bfloat16_rn(b);
    return (unsigned)__bfloat16_as_ushort(ba) |
           ((unsigned)__bfloat16_as_ushort(bb) << 16);
}
__device__ __forceinline__ void mma16816(float* c, unsigned a0, unsigned a1,
                                         unsigned a2, unsigned a3,
                                         unsigned b0, unsigned b1) {
    asm("mma.sync.aligned.m16n8k16.row.col.f32.bf16.bf16.f32 "
        "{%0,%1,%2,%3},{%4,%5,%6,%7},{%8,%9},{%0,%1,%2,%3};"
        : "+f"(c[0]), "+f"(c[1]), "+f"(c[2]), "+f"(c[3])
        : "r"(a0), "r"(a1), "r"(a2), "r"(a3), "r"(b0), "r"(b1));
}

// ---- device scratch (zero-initialized at module load) ----
__device__ int   g_cnt[N_MAX];
__device__ int   g_off[N_MAX + 1];
__device__ int   g_perm[E_MAX];
__device__ int   g_zjs[E_MAX];
__device__ int   g_eatom[E_MAX];
__device__ float g_ZS[256 * 64];
__device__ float g_ZD[256 * 64];
__device__ uint4 g_Wb[24 * 4 * 32];
__device__ float g_accI[N_MAX * 64];
__device__ float g_accA[N_MAX * 64 * 3];
__device__ float g_accS[N_MAX * 64 * 6];

// smem float offsets for fused gemm kernel
#define SS_STR   200
#define OFF_SS   0
#define OFF_WB   25600
#define OFF_ZF   37888
#define OFF_MT   46080
#define OFF_AID  47616
#define OFF_ZI   47744
#define OFF_ZJ   47872
#define OFF_C    48000
#define SM_FLT   48128

// ------------------------------------------------------------------
// Launch 1: ZS/ZD tables + bf16 W fragments + histogram + acc zeroing
// ------------------------------------------------------------------
__global__ void k_pc(const int* __restrict__ ei,
                     const float* __restrict__ emb, const float* __restrict__ e2w,
                     const float* __restrict__ e2b,
                     const float* __restrict__ d1w, const float* __restrict__ d2w,
                     const float* __restrict__ d3w,
                     int n, int nE, int maxz, int Bpre, int Bcnt)
{
    int blk = blockIdx.x, tid = threadIdx.x;
    if (blk < Bpre) {
        __shared__ float er[256];
        int zz = blk * 4 + (tid >> 6);
        int h = tid & 63;
        if (zz < maxz) er[(tid >> 6) * 64 + h] = emb[zz * 64 + h];
        __syncthreads();
        if (zz < maxz) {
            const float* e = er + (tid >> 6) * 64;
            float ss = e2b[h], sd = 0.f;
            #pragma unroll 8
            for (int j = 0; j < 64; j++) {
                ss = fmaf(e2w[h * 128 + j], e[j], ss);
                sd = fmaf(e2w[h * 128 + 64 + j], e[j], sd);
            }
            g_ZS[zz * 64 + h] = ss;
            g_ZD[zz * 64 + h] = sd;
        }
    } else if (blk < Bpre + 12) {
        int i = (blk - Bpre) * 256 + tid;
        int lane = i & 31, kk = (i >> 5) & 3, ntg = i >> 7;
        int g = lane >> 2, c = lane & 3;
        int m = ntg * 8 + g;
        const float* W = (m < 64) ? d1w : (m < 128) ? d2w : d3w;
        int h = m & 63;
        int k0 = kk * 16 + 2 * c;
        float w00 = W[h * 64 + k0],     w01 = W[h * 64 + k0 + 1];
        float w10 = W[h * 64 + k0 + 8], w11 = W[h * 64 + k0 + 9];
        __nv_bfloat16 h00 = __float2bfloat16_rn(w00), h01 = __float2bfloat16_rn(w01);
        __nv_bfloat16 h10 = __float2bfloat16_rn(w10), h11 = __float2bfloat16_rn(w11);
        unsigned bh0 = (unsigned)__bfloat16_as_ushort(h00) |
                       ((unsigned)__bfloat16_as_ushort(h01) << 16);
        unsigned bh1 = (unsigned)__bfloat16_as_ushort(h10) |
                       ((unsigned)__bfloat16_as_ushort(h11) << 16);
        unsigned bl0 = packbf(w00 - __bfloat162float(h00), w01 - __bfloat162float(h01));
        unsigned bl1 = packbf(w10 - __bfloat162float(h10), w11 - __bfloat162float(h11));
        g_Wb[i] = make_uint4(bh0, bh1, bl0, bl1);
    } else if (blk < Bpre + 12 + Bcnt) {
        int e = (blk - Bpre - 12) * 256 + tid;
        if (e < nE) atomicAdd(&g_cnt[ei[e]], 1);
    } else {
        // zero acc arrays (float4)
        int zidx = (blk - Bpre - 12 - Bcnt) * 256 + tid;
        int nI4 = n * 16, nA4 = n * 48, nS4 = n * 96;
        float4 zv = make_float4(0.f, 0.f, 0.f, 0.f);
        if (zidx < nI4) ((float4*)g_accI)[zidx] = zv;
        else if (zidx < nI4 + nA4) ((float4*)g_accA)[zidx - nI4] = zv;
        else if (zidx < nI4 + nA4 + nS4) ((float4*)g_accS)[zidx - nI4 - nA4] = zv;
    }
}

// ------------------------------------------------------------------
// Launch 2: exclusive scan of counts (re-zeroes g_cnt for scatter)
// ------------------------------------------------------------------
__global__ void k_scan(int n) {
    __shared__ int wsum[32];
    int tid = threadIdx.x, lane = tid & 31, wid = tid >> 5;
    const int CH = 16;
    int beg = tid * CH;
    int loc[CH];
    int s = 0;
    if (beg + CH <= n) {
        int4 a0 = *(const int4*)&g_cnt[beg];
        int4 a1 = *(const int4*)&g_cnt[beg + 4];
        int4 a2 = *(const int4*)&g_cnt[beg + 8];
        int4 a3 = *(const int4*)&g_cnt[beg + 12];
        int v[CH] = {a0.x,a0.y,a0.z,a0.w, a1.x,a1.y,a1.z,a1.w,
                     a2.x,a2.y,a2.z,a2.w, a3.x,a3.y,a3.z,a3.w};
        #pragma unroll
        for (int i = 0; i < CH; i++) { loc[i] = s; s += v[i]; }
    } else {
        #pragma unroll
        for (int i = 0; i < CH; i++) {
            loc[i] = s;
            int idx = beg + i;
            if (idx < n) s += g_cnt[idx];
        }
    }
    int inc = s;
    #pragma unroll
    for (int o = 1; o < 32; o <<= 1) {
        int t = __shfl_up_sync(0xffffffffu, inc, o);
        if (lane >= o) inc += t;
    }
    if (lane == 31) wsum[wid] = inc;
    __syncthreads();
    if (wid == 0) {
        int v = wsum[lane];
        #pragma unroll
        for (int o = 1; o < 32; o <<= 1) {
            int t = __shfl_up_sync(0xffffffffu, v, o);
            if (lane >= o) v += t;
        }
        wsum[lane] = v;
    }
    __syncthreads();
    int excl = inc - s + (wid ? wsum[wid - 1] : 0);
    #pragma unroll
    for (int i = 0; i < CH; i++) {
        int idx = beg + i;
        if (idx < n) { g_off[idx] = excl + loc[i]; g_cnt[idx] = 0; }
    }
    if (tid == 1023) g_off[n] = wsum[31];
}

// ------------------------------------------------------------------
// Launch 3: scatter -> perm + zj + src atom (sorted order)
// ------------------------------------------------------------------
__global__ void k_scatter(const int* __restrict__ ei, const int* __restrict__ z, int nE) {
    int e = blockIdx.x * blockDim.x + threadIdx.x;
    if (e < nE) {
        int s = ei[e];
        int pos = g_off[s] + atomicAdd(&g_cnt[s], 1);
        g_perm[pos] = e;
        g_zjs[pos] = z[ei[nE + e]];
        g_eatom[pos] = s;
    }
}

// ------------------------------------------------------------------
// Launch 4 (ncu target): FUSED bf16 GEMM + segment reduction.
// S stays in smem; compact moments flushed via atomicAdd.
// ------------------------------------------------------------------
__global__ __launch_bounds__(128)
void k_gemm(const float* __restrict__ attr, const float* __restrict__ ew,
            const float* __restrict__ evn, const int* __restrict__ z,
            const float* __restrict__ d1b, const float* __restrict__ d2b,
            const float* __restrict__ d3b, int nE)
{
    extern __shared__ float smf[];
    float* sS   = smf + OFF_SS;
    uint4* sWb  = (uint4*)(smf + OFF_WB);
    float* zf   = smf + OFF_ZF;
    float* mt   = smf + OFF_MT;
    int*   sAid = (int*)(smf + OFF_AID);
    int*   sZi  = (int*)(smf + OFF_ZI);
    int*   sZj  = (int*)(smf + OFF_ZJ);
    float* sC   = smf + OFF_C;

    unsigned* aHi = (unsigned*)sS;          // A tiles live in sS region pre-mainloop
    unsigned* aLo = aHi + 128 * 36;

    int tid = threadIdx.x;
    int sBase = blockIdx.x * 128;

    // ---- stage per-edge data ----
    int sIdx = sBase + tid; if (sIdx >= nE) sIdx = nE - 1;
    int e = g_perm[sIdx];
    int aidv = g_eatom[sIdx];
    sAid[tid] = aidv;
    sZi[tid]  = z[aidv];
    sZj[tid]  = g_zjs[sIdx];
    {
        float w = ew[e];
        float C = (w < RC_F) ? 0.5f * (cosf(w * (PI_F / RC_F)) + 1.0f) : 0.0f;
        sC[tid] = C;
        float vx = evn[3 * e + 0], vy = evn[3 * e + 1], vz = evn[3 * e + 2];
        float tr3 = (vx * vx + vy * vy + vz * vz) * (1.0f / 3.0f);
        float* mp = mt + tid * 12;
        mp[0] = vx; mp[1] = vy; mp[2] = vz;
        mp[3] = vx * vx - tr3; mp[4] = vy * vy - tr3; mp[5] = vz * vz - tr3;
        mp[6] = vx * vy; mp[7] = vx * vz; mp[8] = vy * vz;
    }
    // Wb -> smem
    #pragma unroll
    for (int i = 0; i < 24; i++) sWb[i * 128 + tid] = g_Wb[i * 128 + tid];
    // A convert: thread per row
    {
        const float4* src = (const float4*)(attr + (size_t)e * 64);
        #pragma unroll
        for (int k = 0; k < 16; k++) {
            float4 v = src[k];
            int half = k >> 3, q = k & 7;
            unsigned* dh = aHi + tid * 36 + half * 16 + 2 * q;
            unsigned* dl = aLo + tid * 36 + half * 16 + 2 * q;
            __nv_bfloat16 hx = __float2bfloat16_rn(v.x), hy = __float2bfloat16_rn(v.y);
            __nv_bfloat16 hz = __float2bfloat16_rn(v.z), hw = __float2bfloat16_rn(v.w);
            dh[0] = (unsigned)__bfloat16_as_ushort(hx) |
                    ((unsigned)__bfloat16_as_ushort(hy) << 16);
            dh[1] = (unsigned)__bfloat16_as_ushort(hz) |
                    ((unsigned)__bfloat16_as_ushort(hw) << 16);
            dl[0] = packbf(v.x - __bfloat162float(hx), v.y - __bfloat162float(hy));
            dl[1] = packbf(v.z - __bfloat162float(hz), v.w - __bfloat162float(hw));
        }
    }
    __syncthreads();

    // ---- A fragments to registers ----
    int warp = tid >> 5, lane = tid & 31;
    int g = lane >> 2, cc = lane & 3;
    int row0 = warp * 32 + g;
    int row1 = row0 + 16;

    unsigned AH0[4][4], AL0[4][4], AH1[4][4], AL1[4][4];
    #pragma unroll
    for (int kk = 0; kk < 4; kk++) {
        int base = kk * 8 + cc;
        AH0[kk][0] = aHi[row0 * 36 + base];
        AH0[kk][1] = aHi[(row0 + 8) * 36 + base];
        AH0[kk][2] = aHi[row0 * 36 + base + 4];
        AH0[kk][3] = aHi[(row0 + 8) * 36 + base + 4];
        AL0[kk][0] = aLo[row0 * 36 + base];
        AL0[kk][1] = aLo[(row0 + 8) * 36 + base];
        AL0[kk][2] = aLo[row0 * 36 + base + 4];
        AL0[kk][3] = aLo[(row0 + 8) * 36 + base + 4];
        AH1[kk][0] = aHi[row1 * 36 + base];
        AH1[kk][1] = aHi[(row1 + 8) * 36 + base];
        AH1[kk][2] = aHi[row1 * 36 + base + 4];
        AH1[kk][3] = aHi[(row1 + 8) * 36 + base + 4];
        AL1[kk][0] = aLo[row1 * 36 + base];
        AL1[kk][1] = aLo[(row1 + 8) * 36 + base];
        AL1[kk][2] = aLo[row1 * 36 + base + 4];
        AL1[kk][3] = aLo[(row1 + 8) * 36 + base + 4];
    }

    // ---- zf[e][h] = C * (ZS[zi] + ZD[zj]) ----
    {
        const ull* ZSu = (const ull*)g_ZS;
        const ull* ZDu = (const ull*)g_ZD;
        ull* zfu = (ull*)zf;
        #pragma unroll 4
        for (int idx = tid; idx < 4096; idx += 128) {
            int e2 = idx >> 5, hp = idx & 31;
            ull a = ZSu[sZi[e2] * 32 + hp];
            ull b = ZDu[sZj[e2] * 32 + hp];
            zfu[e2 * 32 + hp] = mul2(packdup(sC[e2]), add2(a, b));
        }
    }
    __syncthreads();   // frags loaded + zf ready; sS region may now be overwritten

    // ---- mainloop: mma -> sS ----
    for (int ntg = 0; ntg < 24; ntg++) {
        float c0[4] = {0.f, 0.f, 0.f, 0.f};
        float c1[4] = {0.f, 0.f, 0.f, 0.f};
        #pragma unroll
        for (int kk = 0; kk < 4; kk++) {
            uint4 bb = sWb[(ntg * 4 + kk) * 32 + lane];
            mma16816(c0, AH0[kk][0], AH0[kk][1], AH0[kk][2], AH0[kk][3], bb.x, bb.y);
            mma16816(c1, AH1[kk][0], AH1[kk][1], AH1[kk][2], AH1[kk][3], bb.x, bb.y);
            mma16816(c0, AH0[kk][0], AH0[kk][1], AH0[kk][2], AH0[kk][3], bb.z, bb.w);
            mma16816(c1, AH1[kk][0], AH1[kk][1], AH1[kk][2], AH1[kk][3], bb.z, bb.w);
            mma16816(c0, AL0[kk][0], AL0[kk][1], AL0[kk][2], AL0[kk][3], bb.x, bb.y);
            mma16816(c1, AL1[kk][0], AL1[kk][1], AL1[kk][2], AL1[kk][3], bb.x, bb.y);
        }
        int m = ntg * 8 + 2 * cc;
        *(float2*)&sS[row0 * SS_STR + m]        = make_float2(c0[0], c0[1]);
        *(float2*)&sS[(row0 + 8) * SS_STR + m]  = make_float2(c0[2], c0[3]);
        *(float2*)&sS[(row0 + 16) * SS_STR + m] = make_float2(c1[0], c1[1]);
        *(float2*)&sS[(row0 + 24) * SS_STR + m] = make_float2(c1[2], c1[3]);
    }
    __syncthreads();

    // ---- epilogue: segment reduce over sorted edges ----
    int h = tid & 63, part = tid >> 6;
    int ne = nE - sBase; if (ne > 128) ne = 128;
    float b1v = __ldg(d1b + h), b2v = __ldg(d2b + h), b3v = __ldg(d3b + h);

    int aidCur = sAid[0];
    float a0 = 0.f, a1 = 0.f, a2 = 0.f, a3 = 0.f, a4 = 0.f, a5 = 0.f;

    for (int e2 = 0; e2 < ne; e2++) {
        int aa = sAid[e2];
        if (aa != aidCur) {
            if (part == 0) {
                atomicAdd(&g_accI[aidCur * 64 + h], a0);
                int b = (aidCur * 64 + h) * 3;
                atomicAdd(&g_accA[b + 0], a1);
                atomicAdd(&g_accA[b + 1], a2);
                atomicAdd(&g_accA[b + 2], a3);
            } else {
                int b = (aidCur * 64 + h) * 6;
                atomicAdd(&g_accS[b + 0], a0);
                atomicAdd(&g_accS[b + 1], a1);
                atomicAdd(&g_accS[b + 2], a2);
                atomicAdd(&g_accS[b + 3], a3);
                atomicAdd(&g_accS[b + 4], a4);
                atomicAdd(&g_accS[b + 5], a5);
            }
            a0 = a1 = a2 = a3 = a4 = a5 = 0.f;
            aidCur = aa;
        }
        float zfv = zf[e2 * 64 + h];
        const float* mp = mt + e2 * 12;
        if (part == 0) {
            float g1 = (sS[e2 * SS_STR + h] + b1v) * zfv;
            float g2 = (sS[e2 * SS_STR + 64 + h] + b2v) * zfv;
            a0 += g1;
            a1 = fmaf(g2, mp[0], a1);
            a2 = fmaf(g2, mp[1], a2);
            a3 = fmaf(g2, mp[2], a3);
        } else {
            float g3 = (sS[e2 * SS_STR + 128 + h] + b3v) * zfv;
            a0 = fmaf(g3, mp[3], a0);
            a1 = fmaf(g3, mp[4], a1);
            a2 = fmaf(g3, mp[5], a2);
            a3 = fmaf(g3, mp[6], a3);
            a4 = fmaf(g3, mp[7], a4);
            a5 = fmaf(g3, mp[8], a5);
        }
    }
    if (part == 0) {
        atomicAdd(&g_accI[aidCur * 64 + h], a0);
        int b = (aidCur * 64 + h) * 3;
        atomicAdd(&g_accA[b + 0], a1);
        atomicAdd(&g_accA[b + 1], a2);
        atomicAdd(&g_accA[b + 2], a3);
    } else {
        int b = (aidCur * 64 + h) * 6;
        atomicAdd(&g_accS[b + 0], a0);
        atomicAdd(&g_accS[b + 1], a1);
        atomicAdd(&g_accS[b + 2], a2);
        atomicAdd(&g_accS[b + 3], a3);
        atomicAdd(&g_accS[b + 4], a4);
        atomicAdd(&g_accS[b + 5], a5);
    }
}

// ------------------------------------------------------------------
// Launch 5: tn -> LN -> MLP -> n0 -> diagonal output + g_cnt re-zero
// ------------------------------------------------------------------
__device__ __forceinline__ float sq(float x) { return x * x; }
__device__ __forceinline__ float silu(float x) { return x / (1.0f + expf(-x)); }

__global__ void k_post(const float* __restrict__ lng, const float* __restrict__ lnb,
                       const float* __restrict__ w1, const float* __restrict__ b1,
                       const float* __restrict__ w2, const float* __restrict__ b2,
                       const float* __restrict__ m0, const float* __restrict__ m1,
                       const float* __restrict__ m2, float* __restrict__ out, int n)
{
    extern __shared__ float sm[];
    float* w1T  = sm;
    float* w2nT = w1T + 64 * 128;
    float* m0T  = w2nT + 128 * 64;
    float* msT  = m0T + 64 * 64;
    float* sb1  = msT + 64 * 64;
    float* sb2  = sb1 + 128;
    float* slg  = sb2 + 64;
    float* slb  = slg + 64;
    float* wk   = slb + 64;

    int tid = threadIdx.x;
    for (int i = tid; i < 64 * 128; i += blockDim.x) {
        int j = i >> 7, o = i & 127;
        w1T[i] = w1[o * 64 + j];
    }
    for (int i = tid; i < 128 * 64; i += blockDim.x) {
        int j = i >> 6, h = i & 63;
        w2nT[i] = w2[h * 3 * 128 + j];
    }
    for (int i = tid; i < 64 * 64; i += blockDim.x) {
        int h = i >> 6, k = i & 63;
        m0T[i] = m0[k * 64 + h];
        msT[i] = m1[k * 64 + h] + m2[k * 64 + h];
    }
    for (int i = tid; i < 128; i += blockDim.x) sb1[i] = b1[i];
    for (int i = tid; i < 64; i += blockDim.x) {
        sb2[i] = b2[3 * i]; slg[i] = lng[i]; slb[i] = lnb[i];
    }
    __syncthreads();

    int warp = tid >> 5, lane = tid & 31;
    float* nm  = wk + warp * 320;
    float* h1  = nm + 64;
    float* wkv = h1 + 128;
    const float2* w2n2 = (const float2*)w2nT;
    const float2* m0v  = (const float2*)m0T;
    const float2* msv  = (const float2*)msT;

    for (int atom = blockIdx.x * NW + warp; atom < n; atom += gridDim.x * NW) {
        int h0 = lane * 2;
        int base = atom * 64 + h0;
        float i0a = g_accI[base], i0b = g_accI[base + 1];
        const float* Ap = g_accA + base * 3;
        const float* Sp = g_accS + base * 6;
        float tna = sq(i0a + Sp[0]) + sq(i0a + Sp[1]) + sq(i0a + Sp[2])
                  + 2.0f * (sq(Sp[3]) + sq(Sp[4]) + sq(Sp[5]) + sq(Ap[0]) + sq(Ap[1]) + sq(Ap[2]));
        float tnb = sq(i0b + Sp[6]) + sq(i0b + Sp[7]) + sq(i0b + Sp[8])
                  + 2.0f * (sq(Sp[9]) + sq(Sp[10]) + sq(Sp[11]) + sq(Ap[3]) + sq(Ap[4]) + sq(Ap[5]));
        wkv[h0] = i0a; wkv[h0 + 1] = i0b;

        float s = tna + tnb;
        for (int o = 16; o; o >>= 1) s += __shfl_xor_sync(0xffffffffu, s, o);
        float mu = s * (1.0f / 64.0f);
        float da = tna - mu, db = tnb - mu;
        float vs = da * da + db * db;
        for (int o = 16; o; o >>= 1) vs += __shfl_xor_sync(0xffffffffu, vs, o);
        float inv = rsqrtf(vs * (1.0f / 64.0f) + 1e-5f);
        nm[h0]     = da * inv * slg[h0] + slb[h0];
        nm[h0 + 1] = db * inv * slg[h0 + 1] + slb[h0 + 1];
        __syncwarp();

        #pragma unroll
        for (int p = 0; p < 4; p++) {
            int o = lane + 32 * p;
            float acc = sb1[o];
            #pragma unroll 8
            for (int j = 0; j < 64; j++) acc = fmaf(w1T[j * 128 + o], nm[j], acc);
            h1[o] = silu(acc);
        }
        __syncwarp();

        float2 acc2 = ((const float2*)sb2)[lane];
        #pragma unroll 8
        for (int j = 0; j < 128; j++) {
            float hv = h1[j];
            float2 wv = w2n2[j * 32 + lane];
            acc2.x = fmaf(wv.x, hv, acc2.x);
            acc2.y = fmaf(wv.y, hv, acc2.y);
        }
        float n0x = silu(acc2.x), n0y = silu(acc2.y);

        float2 d1 = {0.f, 0.f};
        #pragma unroll 8
        for (int h = 0; h < 64; h++) {
            float a = wkv[h];
            float2 m = m0v[h * 32 + lane];
            d1.x = fmaf(m.x, a, d1.x);
            d1.y = fmaf(m.y, a, d1.y);
        }
        d1.x *= n0x; d1.y *= n0y;
        __syncwarp();
        wkv[h0] = d1.x; wkv[h0 + 1] = d1.y;
        __syncwarp();

        float2 tt = {0.f, 0.f};
        #pragma unroll 8
        for (int h = 0; h < 64; h++) {
            float d = wkv[h];
            float2 m = msv[h * 32 + lane];
            tt.x = fmaf(m.x, d, tt.x);
            tt.y = fmaf(m.y, d, tt.y);
        }
        float vx = d1.x + n0x * tt.x;
        float vy = d1.y + n0y * tt.y;

        float2* o = (float2*)(out + (size_t)(atom * 64 + h0) * 9);
        o[0] = make_float2(vx, 0.f);
        o[1] = make_float2(0.f, 0.f);
        o[2] = make_float2(vx, 0.f);
        o[3] = make_float2(0.f, 0.f);
        o[4] = make_float2(vx, vy);
        o[5] = make_float2(0.f, 0.f);
        o[6] = make_float2(0.f, vy);
        o[7] = make_float2(0.f, 0.f);
        o[8] = make_float2(0.f, vy);
        __syncwarp();
    }

    // re-zero g_cnt for the next replay
    int gt = blockIdx.x * blockDim.x + threadIdx.x;
    int tot = gridDim.x * blockDim.x;
    for (int i = gt; i < n; i += tot) g_cnt[i] = 0;
}

// ------------------------------------------------------------------
extern "C" void kernel_launch(void* const* d_in, const int* in_sizes, int n_in,
                              void* d_out, int out_size)
{
    const int*   z    = (const int*)d_in[0];
    const int*   ei   = (const int*)d_in[1];
    const float* ew   = (const float*)d_in[2];
    const float* evn  = (const float*)d_in[3];
    const float* attr = (const float*)d_in[4];
    const float* emb  = (const float*)d_in[5];
    const float* e2w  = (const float*)d_in[6];
    const float* e2b  = (const float*)d_in[7];
    const float* d1w  = (const float*)d_in[8];
    const float* d1b  = (const float*)d_in[9];
    const float* d2w  = (const float*)d_in[10];
    const float* d2b  = (const float*)d_in[11];
    const float* d3w  = (const float*)d_in[12];
    const float* d3b  = (const float*)d_in[13];
    const float* lng  = (const float*)d_in[14];
    const float* lnb  = (const float*)d_in[15];
    const float* w1   = (const float*)d_in[16];
    const float* b1   = (const float*)d_in[17];
    const float* w2   = (const float*)d_in[18];
    const float* b2   = (const float*)d_in[19];
    const float* m0   = (const float*)d_in[20];
    const float* m1   = (const float*)d_in[21];
    const float* m2   = (const float*)d_in[22];
    float* out = (float*)d_out;

    int n    = in_sizes[0];
    int nE   = in_sizes[2];
    int maxz = in_sizes[5] / 64;
    if (maxz > 256) maxz = 256;

    int Bpre = (maxz + 3) / 4;
    int Bcnt = (nE + 255) / 256;
    int Bz   = (160 * n + 255) / 256;

    size_t smemG = (size_t)SM_FLT * sizeof(float);               // ~192.5 KB
    size_t smemP = (size_t)(64 * 128 + 128 * 64 + 2 * 64 * 64 + 128 + 3 * 64 + NW * 320)
                   * sizeof(float);                              // ~110 KB
    cudaFuncSetAttribute(k_gemm, cudaFuncAttributeMaxDynamicSharedMemorySize, (int)smemG);
    cudaFuncSetAttribute(k_post, cudaFuncAttributeMaxDynamicSharedMemorySize, (int)smemP);

    k_pc<<<Bpre + 12 + Bcnt + Bz, 256>>>(ei, emb, e2w, e2b, d1w, d2w, d3w,
                                         n, nE, maxz, Bpre, Bcnt);
    k_scan<<<1, 1024>>>(n);
    k_scatter<<<(nE + 255) / 256, 256>>>(ei, z, nE);
    k_gemm<<<(nE + 127) / 128, 128, smemG>>>(attr, ew, evn, z,
                                             d1b, d2b, d3b, nE);  // launch #4 -> ncu
    k_post<<<304, NW * 32, smemP>>>(lng, lnb, w1, b1, w2, b2, m0, m1, m2, out, n);
}

// round 15
// speedup vs baseline: 1.1180x; 1.1180x over previous
#include <cuda_runtime.h>
#include <cuda_bf16.h>
#include <math.h>

#define N_MAX 10000
#define E_MAX 160000
#define RC_F 4.5f
#define PI_F 3.14159265358979323846f

typedef unsigned long long ull;

__device__ __forceinline__ ull fma2(ull a, ull b, ull c) {
    ull d; asm("fma.rn.f32x2 %0,%1,%2,%3;" : "=l"(d) : "l"(a), "l"(b), "l"(c)); return d;
}
__device__ __forceinline__ ull mul2(ull a, ull b) {
    ull d; asm("mul.rn.f32x2 %0,%1,%2;" : "=l"(d) : "l"(a), "l"(b)); return d;
}
__device__ __forceinline__ ull add2(ull a, ull b) {
    ull d; asm("add.rn.f32x2 %0,%1,%2;" : "=l"(d) : "l"(a), "l"(b)); return d;
}
__device__ __forceinline__ ull packdup(float x) {
    ull d; asm("mov.b64 %0,{%1,%1};" : "=l"(d) : "f"(x)); return d;
}
__device__ __forceinline__ float2 unpack2(ull a) {
    float2 v; asm("mov.b64 {%0,%1},%2;" : "=f"(v.x), "=f"(v.y) : "l"(a)); return v;
}
__device__ __forceinline__ unsigned packbf(float a, float b) {
    __nv_bfloat16 ba = __float2bfloat16_rn(a), bb = __float2bfloat16_rn(b);
    return (unsigned)__bfloat16_as_ushort(ba) |
           ((unsigned)__bfloat16_as_ushort(bb) << 16);
}
__device__ __forceinline__ void mma16816(float* c, unsigned a0, unsigned a1,
                                         unsigned a2, unsigned a3,
                                         unsigned b0, unsigned b1) {
    asm("mma.sync.aligned.m16n8k16.row.col.f32.bf16.bf16.f32 "
        "{%0,%1,%2,%3},{%4,%5,%6,%7},{%8,%9},{%0,%1,%2,%3};"
        : "+f"(c[0]), "+f"(c[1]), "+f"(c[2]), "+f"(c[3])
        : "r"(a0), "r"(a1), "r"(a2), "r"(a3), "r"(b0), "r"(b1));
}

// ---- device scratch (zero-initialized at module load) ----
__device__ int   g_cnt[N_MAX];
__device__ int   g_off[N_MAX + 1];
__device__ int   g_perm[E_MAX];
__device__ int   g_zjs[E_MAX];
__device__ int   g_flag;
__device__ float g_ZS[256 * 64];
__device__ float g_ZD[256 * 64];
__device__ float g_meta[(size_t)(E_MAX + 128) * 12];   // SORTED order
__device__ uint4 g_Wb[24 * 4 * 32];                    // bf16 hi/lo B fragments
__device__ float g_S[(size_t)(E_MAX + 128) * 192];     // SORTED order

// ------------------------------------------------------------------
// Launch 1: ZS/ZD tables + bf16 W fragment prep + histogram count
// ------------------------------------------------------------------
__global__ void k_pc(const int* __restrict__ ei,
                     const float* __restrict__ emb, const float* __restrict__ e2w,
                     const float* __restrict__ e2b,
                     const float* __restrict__ d1w, const float* __restrict__ d2w,
                     const float* __restrict__ d3w,
                     int nE, int maxz, int Bpre)
{
    int blk = blockIdx.x, tid = threadIdx.x;
    if (blk < Bpre) {
        __shared__ float er[256];
        int zz = blk * 4 + (tid >> 6);
        int h = tid & 63;
        if (zz < maxz) er[(tid >> 6) * 64 + h] = emb[zz * 64 + h];
        __syncthreads();
        if (zz < maxz) {
            const float* e = er + (tid >> 6) * 64;
            float ss = e2b[h], sd = 0.f;
            #pragma unroll 8
            for (int j = 0; j < 64; j++) {
                ss = fmaf(e2w[h * 128 + j], e[j], ss);
                sd = fmaf(e2w[h * 128 + 64 + j], e[j], sd);
            }
            g_ZS[zz * 64 + h] = ss;
            g_ZD[zz * 64 + h] = sd;
        }
    } else if (blk < Bpre + 12) {
        int i = (blk - Bpre) * 256 + tid;
        int lane = i & 31, kk = (i >> 5) & 3, ntg = i >> 7;
        int g = lane >> 2, c = lane & 3;
        int m = ntg * 8 + g;
        const float* W = (m < 64) ? d1w : (m < 128) ? d2w : d3w;
        int h = m & 63;
        int k0 = kk * 16 + 2 * c;
        float w00 = W[h * 64 + k0],     w01 = W[h * 64 + k0 + 1];
        float w10 = W[h * 64 + k0 + 8], w11 = W[h * 64 + k0 + 9];
        __nv_bfloat16 h00 = __float2bfloat16_rn(w00), h01 = __float2bfloat16_rn(w01);
        __nv_bfloat16 h10 = __float2bfloat16_rn(w10), h11 = __float2bfloat16_rn(w11);
        unsigned bh0 = (unsigned)__bfloat16_as_ushort(h00) |
                       ((unsigned)__bfloat16_as_ushort(h01) << 16);
        unsigned bh1 = (unsigned)__bfloat16_as_ushort(h10) |
                       ((unsigned)__bfloat16_as_ushort(h11) << 16);
        unsigned bl0 = packbf(w00 - __bfloat162float(h00), w01 - __bfloat162float(h01));
        unsigned bl1 = packbf(w10 - __bfloat162float(h10), w11 - __bfloat162float(h11));
        g_Wb[i] = make_uint4(bh0, bh1, bl0, bl1);
    } else {
        int e = (blk - Bpre - 12) * 256 + tid;
        if (e < nE) atomicAdd(&g_cnt[ei[e]], 1);
    }
}

// ------------------------------------------------------------------
// Launch 2: fused scan (block 0) + scatter (all blocks, flag-gated)
// 1024 threads per block.
// ------------------------------------------------------------------
__global__ __launch_bounds__(1024)
void k_ss(const int* __restrict__ ei, const int* __restrict__ z, int nE, int n)
{
    int tid = threadIdx.x, lane = tid & 31, wid = tid >> 5;

    if (blockIdx.x == 0) {
        __shared__ int wsum[32];
        const int CH = 16;
        int beg = tid * CH;
        int loc[CH];
        int s = 0;
        if (beg + CH <= n) {
            int4 a0 = *(const int4*)&g_cnt[beg];
            int4 a1 = *(const int4*)&g_cnt[beg + 4];
            int4 a2 = *(const int4*)&g_cnt[beg + 8];
            int4 a3 = *(const int4*)&g_cnt[beg + 12];
            int v[CH] = {a0.x,a0.y,a0.z,a0.w, a1.x,a1.y,a1.z,a1.w,
                         a2.x,a2.y,a2.z,a2.w, a3.x,a3.y,a3.z,a3.w};
            #pragma unroll
            for (int i = 0; i < CH; i++) { loc[i] = s; s += v[i]; }
        } else {
            #pragma unroll
            for (int i = 0; i < CH; i++) {
                loc[i] = s;
                int idx = beg + i;
                if (idx < n) s += g_cnt[idx];
            }
        }
        int inc = s;
        #pragma unroll
        for (int o = 1; o < 32; o <<= 1) {
            int t = __shfl_up_sync(0xffffffffu, inc, o);
            if (lane >= o) inc += t;
        }
        if (lane == 31) wsum[wid] = inc;
        __syncthreads();
        if (wid == 0) {
            int v = wsum[lane];
            #pragma unroll
            for (int o = 1; o < 32; o <<= 1) {
                int t = __shfl_up_sync(0xffffffffu, v, o);
                if (lane >= o) v += t;
            }
            wsum[lane] = v;
        }
        __syncthreads();
        int excl = inc - s + (wid ? wsum[wid - 1] : 0);
        #pragma unroll
        for (int i = 0; i < CH; i++) {
            int idx = beg + i;
            if (idx < n) { g_off[idx] = excl + loc[i]; g_cnt[idx] = 0; }
        }
        if (tid == 1023) g_off[n] = wsum[31];
        __syncthreads();
        __threadfence();
        if (tid == 0) atomicExch(&g_flag, 1);
    }

    // gate: wait for scan completion
    if (tid == 0) {
        while (atomicAdd(&g_flag, 0) == 0) { }
    }
    __syncthreads();

    int e = blockIdx.x * 1024 + tid;
    if (e < nE) {
        int s = ei[e];
        int pos = g_off[s] + atomicAdd(&g_cnt[s], 1);
        g_perm[pos] = e;
        g_zjs[pos] = z[ei[nE + e]];
    }
}

// ------------------------------------------------------------------
// Launch 3: bf16 hi/lo GEMM, SORTED order. (R13-proven shape)
// ------------------------------------------------------------------
__global__ __launch_bounds__(128)
void k_gemm(const float* __restrict__ attr, const float* __restrict__ ew,
            const float* __restrict__ evn, int nE)
{
    extern __shared__ unsigned smu[];
    unsigned* aHi = smu;                 // 128 * 36 packed bf16x2
    unsigned* aLo = smu + 128 * 36;

    int tid = threadIdx.x;
    int sBase = blockIdx.x * 128;

    {
        int s = sBase + tid;
        if (s < nE) {
            int e = g_perm[s];
            float w = ew[e];
            float C = (w < RC_F) ? 0.5f * (cosf(w * (PI_F / RC_F)) + 1.0f) : 0.0f;
            float vx = evn[3 * e + 0], vy = evn[3 * e + 1], vz = evn[3 * e + 2];
            float tr3 = (vx * vx + vy * vy + vz * vz) * (1.0f / 3.0f);
            float4* mp = (float4*)(g_meta + (size_t)s * 12);
            mp[0] = make_float4(C, vx, vy, vz);
            mp[1] = make_float4(vx * vx - tr3, vy * vy - tr3, vz * vz - tr3, vx * vy);
            mp[2] = make_float4(vx * vz, vy * vz, 0.f, 0.f);
        }
    }

    {
        int r = tid;
        int srow = sBase + r; if (srow >= nE) srow = nE - 1;
        int e = g_perm[srow];
        const float4* src = (const float4*)(attr + (size_t)e * 64);
        #pragma unroll
        for (int k = 0; k < 16; k++) {
            float4 v = src[k];
            int half = k >> 3, q = k & 7;
            unsigned* dh = aHi + r * 36 + half * 16 + 2 * q;
            unsigned* dl = aLo + r * 36 + half * 16 + 2 * q;
            __nv_bfloat16 hx = __float2bfloat16_rn(v.x), hy = __float2bfloat16_rn(v.y);
            __nv_bfloat16 hz = __float2bfloat16_rn(v.z), hw = __float2bfloat16_rn(v.w);
            dh[0] = (unsigned)__bfloat16_as_ushort(hx) |
                    ((unsigned)__bfloat16_as_ushort(hy) << 16);
            dh[1] = (unsigned)__bfloat16_as_ushort(hz) |
                    ((unsigned)__bfloat16_as_ushort(hw) << 16);
            dl[0] = packbf(v.x - __bfloat162float(hx), v.y - __bfloat162float(hy));
            dl[1] = packbf(v.z - __bfloat162float(hz), v.w - __bfloat162float(hw));
        }
    }
    __syncthreads();

    int warp = tid >> 5, lane = tid & 31;
    int g = lane >> 2, cc = lane & 3;
    int row0 = warp * 32 + g;
    int row1 = row0 + 16;
    size_t eRow0 = (size_t)sBase + row0;

    unsigned AH0[4][4], AL0[4][4], AH1[4][4], AL1[4][4];
    #pragma unroll
    for (int kk = 0; kk < 4; kk++) {
        int base = kk * 8 + cc;
        AH0[kk][0] = aHi[row0 * 36 + base];
        AH0[kk][1] = aHi[(row0 + 8) * 36 + base];
        AH0[kk][2] = aHi[row0 * 36 + base + 4];
        AH0[kk][3] = aHi[(row0 + 8) * 36 + base + 4];
        AL0[kk][0] = aLo[row0 * 36 + base];
        AL0[kk][1] = aLo[(row0 + 8) * 36 + base];
        AL0[kk][2] = aLo[row0 * 36 + base + 4];
        AL0[kk][3] = aLo[(row0 + 8) * 36 + base + 4];
        AH1[kk][0] = aHi[row1 * 36 + base];
        AH1[kk][1] = aHi[(row1 + 8) * 36 + base];
        AH1[kk][2] = aHi[row1 * 36 + base + 4];
        AH1[kk][3] = aHi[(row1 + 8) * 36 + base + 4];
        AL1[kk][0] = aLo[row1 * 36 + base];
        AL1[kk][1] = aLo[(row1 + 8) * 36 + base];
        AL1[kk][2] = aLo[row1 * 36 + base + 4];
        AL1[kk][3] = aLo[(row1 + 8) * 36 + base + 4];
    }

    for (int ntg = 0; ntg < 24; ntg++) {
        float c0[4] = {0.f, 0.f, 0.f, 0.f};
        float c1[4] = {0.f, 0.f, 0.f, 0.f};
        #pragma unroll
        for (int kk = 0; kk < 4; kk++) {
            uint4 bb = __ldg(&g_Wb[(ntg * 4 + kk) * 32 + lane]);
            mma16816(c0, AH0[kk][0], AH0[kk][1], AH0[kk][2], AH0[kk][3], bb.x, bb.y);
            mma16816(c1, AH1[kk][0], AH1[kk][1], AH1[kk][2], AH1[kk][3], bb.x, bb.y);
            mma16816(c0, AH0[kk][0], AH0[kk][1], AH0[kk][2], AH0[kk][3], bb.z, bb.w);
            mma16816(c1, AH1[kk][0], AH1[kk][1], AH1[kk][2], AH1[kk][3], bb.z, bb.w);
            mma16816(c0, AL0[kk][0], AL0[kk][1], AL0[kk][2], AL0[kk][3], bb.x, bb.y);
            mma16816(c1, AL1[kk][0], AL1[kk][1], AL1[kk][2], AL1[kk][3], bb.x, bb.y);
        }
        int m = ntg * 8 + 2 * cc;
        *(float2*)&g_S[eRow0 * 192 + m]        = make_float2(c0[0], c0[1]);
        *(float2*)&g_S[(eRow0 + 8) * 192 + m]  = make_float2(c0[2], c0[3]);
        *(float2*)&g_S[(eRow0 + 16) * 192 + m] = make_float2(c1[0], c1[1]);
        *(float2*)&g_S[(eRow0 + 24) * 192 + m] = make_float2(c1[2], c1[3]);
    }
}

// ------------------------------------------------------------------
// Launch 4 (ncu target): fused reduce + LN + MLP + diagonal output.
// 128 threads/block: reg cap 512 -> NO spills possible. 2 blocks/SM (smem).
// ------------------------------------------------------------------
__device__ __forceinline__ float sq(float x) { return x * x; }
__device__ __forceinline__ float silu(float x) { return x / (1.0f + expf(-x)); }

struct Acc { ull I, Ax, Ay, Az, Sxx, Syy, Szz, Sxy, Sxz, Syz; };

__global__ __launch_bounds__(128)
void k_rp(const int* __restrict__ z,
          const float* __restrict__ d1b, const float* __restrict__ d2b,
          const float* __restrict__ d3b,
          const float* __restrict__ lng, const float* __restrict__ lnb,
          const float* __restrict__ w1, const float* __restrict__ b1,
          const float* __restrict__ w2, const float* __restrict__ b2,
          const float* __restrict__ m0, const float* __restrict__ m1,
          const float* __restrict__ m2, float* __restrict__ out, int n)
{
    extern __shared__ float sm[];
    float* w1T  = sm;               // [j(64)][o(128)]
    float* w2nT = w1T + 64 * 128;   // [j(128)][h(64)]
    float* m0T  = w2nT + 128 * 64;  // [h][k]
    float* msT  = m0T + 64 * 64;    // [h][k] of m1+m2
    float* sb1  = msT + 64 * 64;    // 128
    float* sb2  = sb1 + 128;        // 64
    float* slg  = sb2 + 64;
    float* slb  = slg + 64;
    float* wk   = slb + 64;         // 4 warps * 192

    int tid = threadIdx.x;
    for (int i = tid; i < 64 * 128; i += blockDim.x) {
        int j = i >> 7, o = i & 127;
        w1T[i] = w1[o * 64 + j];
    }
    for (int i = tid; i < 128 * 64; i += blockDim.x) {
        int j = i >> 6, h = i & 63;
        w2nT[i] = w2[h * 3 * 128 + j];
    }
    for (int i = tid; i < 64 * 64; i += blockDim.x) {
        int h = i >> 6, k = i & 63;
        m0T[i] = m0[k * 64 + h];
        msT[i] = m1[k * 64 + h] + m2[k * 64 + h];
    }
    for (int i = tid; i < 128; i += blockDim.x) sb1[i] = b1[i];
    for (int i = tid; i < 64; i += blockDim.x) {
        sb2[i] = b2[3 * i]; slg[i] = lng[i]; slb[i] = lnb[i];
    }
    __syncthreads();

    int warp = tid >> 5, lane = tid & 31;
    float* nm  = wk + warp * 192;
    float* h1  = nm + 64;
    const float2* w2n2 = (const float2*)w2nT;
    const float2* m0v  = (const float2*)m0T;
    const float2* msv  = (const float2*)msT;

    ull bias1 = ((const ull*)d1b)[lane];
    ull bias2 = ((const ull*)d2b)[lane];
    ull bias3 = ((const ull*)d3b)[lane];

    int gwarp  = blockIdx.x * 4 + warp;
    int nwarps = gridDim.x * 4;

    for (int atom = gwarp; atom < n; atom += nwarps) {
        int e0 = g_off[atom], e1 = g_off[atom + 1];
        Acc A = {0ull,0ull,0ull,0ull,0ull,0ull,0ull,0ull,0ull,0ull};

        if (e0 < e1) {
            ull zS2 = ((const ull*)g_ZS)[z[atom] * 32 + lane];
            int zj0 = __ldg(g_zjs + e0);
            int i1 = e0 + 1 < e1 ? e0 + 1 : e1 - 1;
            int zj1 = __ldg(g_zjs + i1);
            for (int s = e0; s < e1; s += 2) {
                ull zd0 = __ldg(((const ull*)g_ZD) + zj0 * 32 + lane);
                ull zd1 = __ldg(((const ull*)g_ZD) + zj1 * 32 + lane);
                int sb = s + 1 < e1 ? s + 1 : e1 - 1;
                const ull* sp0 = (const ull*)(g_S + (size_t)s * 192);
                const ull* sp1 = (const ull*)(g_S + (size_t)sb * 192);
                ull sa1 = __ldg(sp0 + lane);
                ull sa2 = __ldg(sp0 + 32 + lane);
                ull sa3 = __ldg(sp0 + 64 + lane);
                ull sb1_ = __ldg(sp1 + lane);
                ull sb2_ = __ldg(sp1 + 32 + lane);
                ull sb3_ = __ldg(sp1 + 64 + lane);
                const float4* mp0 = (const float4*)(g_meta + (size_t)s * 12);
                const float4* mp1 = (const float4*)(g_meta + (size_t)sb * 12);
                float4 mA0 = __ldg(mp0), mB0 = __ldg(mp0 + 1);
                float2 mC0 = __ldg((const float2*)(mp0 + 2));
                float4 mA1 = __ldg(mp1), mB1 = __ldg(mp1 + 1);
                float2 mC1 = __ldg((const float2*)(mp1 + 2));

                int p0 = s + 2 < e1 ? s + 2 : e1 - 1;
                int p1 = s + 3 < e1 ? s + 3 : e1 - 1;
                zj0 = __ldg(g_zjs + p0);
                zj1 = __ldg(g_zjs + p1);

                {
                    ull zfac = mul2(packdup(mA0.x), add2(zS2, zd0));
                    ull g1 = mul2(add2(sa1, bias1), zfac);
                    ull g2 = mul2(add2(sa2, bias2), zfac);
                    ull g3 = mul2(add2(sa3, bias3), zfac);
                    A.I   = add2(A.I, g1);
                    A.Ax  = fma2(g2, packdup(mA0.y), A.Ax);
                    A.Ay  = fma2(g2, packdup(mA0.z), A.Ay);
                    A.Az  = fma2(g2, packdup(mA0.w), A.Az);
                    A.Sxx = fma2(g3, packdup(mB0.x), A.Sxx);
                    A.Syy = fma2(g3, packdup(mB0.y), A.Syy);
                    A.Szz = fma2(g3, packdup(mB0.z), A.Szz);
                    A.Sxy = fma2(g3, packdup(mB0.w), A.Sxy);
                    A.Sxz = fma2(g3, packdup(mC0.x), A.Sxz);
                    A.Syz = fma2(g3, packdup(mC0.y), A.Syz);
                }
                if (s + 1 < e1) {
                    ull zfac = mul2(packdup(mA1.x), add2(zS2, zd1));
                    ull g1 = mul2(add2(sb1_, bias1), zfac);
                    ull g2 = mul2(add2(sb2_, bias2), zfac);
                    ull g3 = mul2(add2(sb3_, bias3), zfac);
                    A.I   = add2(A.I, g1);
                    A.Ax  = fma2(g2, packdup(mA1.y), A.Ax);
                    A.Ay  = fma2(g2, packdup(mA1.z), A.Ay);
                    A.Az  = fma2(g2, packdup(mA1.w), A.Az);
                    A.Sxx = fma2(g3, packdup(mB1.x), A.Sxx);
                    A.Syy = fma2(g3, packdup(mB1.y), A.Syy);
                    A.Szz = fma2(g3, packdup(mB1.z), A.Szz);
                    A.Sxy = fma2(g3, packdup(mB1.w), A.Sxy);
                    A.Sxz = fma2(g3, packdup(mC1.x), A.Sxz);
                    A.Syz = fma2(g3, packdup(mC1.y), A.Syz);
                }
            }
        }

        // ---- post: tn -> LN -> MLP -> n0 -> diagonal out ----
        float2 vI  = unpack2(A.I);
        float2 vAx = unpack2(A.Ax), vAy = unpack2(A.Ay), vAz = unpack2(A.Az);
        float2 vSxx = unpack2(A.Sxx), vSyy = unpack2(A.Syy), vSzz = unpack2(A.Szz);
        float2 vSxy = unpack2(A.Sxy), vSxz = unpack2(A.Sxz), vSyz = unpack2(A.Syz);

        int h0 = lane * 2;
        float tna = sq(vI.x + vSxx.x) + sq(vI.x + vSyy.x) + sq(vI.x + vSzz.x)
                  + 2.0f * (sq(vSxy.x) + sq(vSxz.x) + sq(vSyz.x)
                          + sq(vAx.x) + sq(vAy.x) + sq(vAz.x));
        float tnb = sq(vI.y + vSxx.y) + sq(vI.y + vSyy.y) + sq(vI.y + vSzz.y)
                  + 2.0f * (sq(vSxy.y) + sq(vSxz.y) + sq(vSyz.y)
                          + sq(vAx.y) + sq(vAy.y) + sq(vAz.y));

        float s = tna + tnb;
        for (int o = 16; o; o >>= 1) s += __shfl_xor_sync(0xffffffffu, s, o);
        float mu = s * (1.0f / 64.0f);
        float da = tna - mu, db = tnb - mu;
        float vs = da * da + db * db;
        for (int o = 16; o; o >>= 1) vs += __shfl_xor_sync(0xffffffffu, vs, o);
        float inv = rsqrtf(vs * (1.0f / 64.0f) + 1e-5f);
        nm[h0]     = da * inv * slg[h0] + slb[h0];
        nm[h0 + 1] = db * inv * slg[h0 + 1] + slb[h0 + 1];
        __syncwarp();

        #pragma unroll
        for (int p = 0; p < 4; p++) {
            int o = lane + 32 * p;
            float acc = sb1[o];
            #pragma unroll 8
            for (int j = 0; j < 64; j++) acc = fmaf(w1T[j * 128 + o], nm[j], acc);
            h1[o] = silu(acc);
        }
        __syncwarp();

        nm[h0] = vI.x; nm[h0 + 1] = vI.y;

        float2 acc2 = ((const float2*)sb2)[lane];
        #pragma unroll 8
        for (int j = 0; j < 128; j++) {
            float hv = h1[j];
            float2 wv = w2n2[j * 32 + lane];
            acc2.x = fmaf(wv.x, hv, acc2.x);
            acc2.y = fmaf(wv.y, hv, acc2.y);
        }
        float n0x = silu(acc2.x), n0y = silu(acc2.y);
        __syncwarp();

        float2 d1 = {0.f, 0.f};
        #pragma unroll 8
        for (int h = 0; h < 64; h++) {
            float a = nm[h];
            float2 m = m0v[h * 32 + lane];
            d1.x = fmaf(m.x, a, d1.x);
            d1.y = fmaf(m.y, a, d1.y);
        }
        d1.x *= n0x; d1.y *= n0y;
        __syncwarp();
        nm[h0] = d1.x; nm[h0 + 1] = d1.y;
        __syncwarp();

        float2 tt = {0.f, 0.f};
        #pragma unroll 8
        for (int h = 0; h < 64; h++) {
            float d = nm[h];
            float2 m = msv[h * 32 + lane];
            tt.x = fmaf(m.x, d, tt.x);
            tt.y = fmaf(m.y, d, tt.y);
        }
        float vx = d1.x + n0x * tt.x;
        float vy = d1.y + n0y * tt.y;

        float2* o = (float2*)(out + (size_t)(atom * 64 + h0) * 9);
        o[0] = make_float2(vx, 0.f);
        o[1] = make_float2(0.f, 0.f);
        o[2] = make_float2(vx, 0.f);
        o[3] = make_float2(0.f, 0.f);
        o[4] = make_float2(vx, vy);
        o[5] = make_float2(0.f, 0.f);
        o[6] = make_float2(0.f, vy);
        o[7] = make_float2(0.f, 0.f);
        o[8] = make_float2(0.f, vy);
        __syncwarp();
    }

    // re-zero g_cnt and g_flag for the next replay
    int gt = blockIdx.x * blockDim.x + threadIdx.x;
    int tot = gridDim.x * blockDim.x;
    for (int i = gt; i < n; i += tot) g_cnt[i] = 0;
    if (gt == 0) g_flag = 0;
}

// ------------------------------------------------------------------
extern "C" void kernel_launch(void* const* d_in, const int* in_sizes, int n_in,
                              void* d_out, int out_size)
{
    const int*   z    = (const int*)d_in[0];
    const int*   ei   = (const int*)d_in[1];
    const float* ew   = (const float*)d_in[2];
    const float* evn  = (const float*)d_in[3];
    const float* attr = (const float*)d_in[4];
    const float* emb  = (const float*)d_in[5];
    const float* e2w  = (const float*)d_in[6];
    const float* e2b  = (const float*)d_in[7];
    const float* d1w  = (const float*)d_in[8];
    const float* d1b  = (const float*)d_in[9];
    const float* d2w  = (const float*)d_in[10];
    const float* d2b  = (const float*)d_in[11];
    const float* d3w  = (const float*)d_in[12];
    const float* d3b  = (const float*)d_in[13];
    const float* lng  = (const float*)d_in[14];
    const float* lnb  = (const float*)d_in[15];
    const float* w1   = (const float*)d_in[16];
    const float* b1   = (const float*)d_in[17];
    const float* w2   = (const float*)d_in[18];
    const float* b2   = (const float*)d_in[19];
    const float* m0   = (const float*)d_in[20];
    const float* m1   = (const float*)d_in[21];
    const float* m2   = (const float*)d_in[22];
    float* out = (float*)d_out;

    int n    = in_sizes[0];
    int nE   = in_sizes[2];
    int maxz = in_sizes[5] / 64;
    if (maxz > 256) maxz = 256;

    int Bpre = (maxz + 3) / 4;
    int Bcnt = (nE + 255) / 256;
    int Bss  = (nE + 1023) / 1024;

    size_t smemG = (size_t)(2 * 128 * 36) * sizeof(unsigned);   // 36864 B
    size_t smemR = (size_t)(64 * 128 + 128 * 64 + 2 * 64 * 64 + 128 + 3 * 64 + 4 * 192)
                   * sizeof(float);                              // ~102 KB
    cudaFuncSetAttribute(k_gemm, cudaFuncAttributeMaxDynamicSharedMemorySize, (int)smemG);
    cudaFuncSetAttribute(k_rp,   cudaFuncAttributeMaxDynamicSharedMemorySize, (int)smemR);

    k_pc<<<Bpre + 12 + Bcnt, 256>>>(ei, emb, e2w, e2b, d1w, d2w, d3w, nE, maxz, Bpre);
    k_ss<<<Bss, 1024>>>(ei, z, nE, n);
    k_gemm<<<(nE + 127) / 128, 128, smemG>>>(attr, ew, evn, nE);
    k_rp<<<296, 128, smemR>>>(z, d1b, d2b, d3b, lng, lnb, w1, b1, w2, b2,
                              m0, m1, m2, out, n);                 // launch #4 -> ncu
}

// round 16
// speedup vs baseline: 1.3906x; 1.2439x over previous
#include <cuda_runtime.h>
#include <cuda_bf16.h>
#include <math.h>

#define N_MAX 10000
#define E_MAX 160000
#define NW 8
#define RC_F 4.5f
#define PI_F 3.14159265358979323846f

typedef unsigned long long ull;

__device__ __forceinline__ ull fma2(ull a, ull b, ull c) {
    ull d; asm("fma.rn.f32x2 %0,%1,%2,%3;" : "=l"(d) : "l"(a), "l"(b), "l"(c)); return d;
}
__device__ __forceinline__ ull mul2(ull a, ull b) {
    ull d; asm("mul.rn.f32x2 %0,%1,%2;" : "=l"(d) : "l"(a), "l"(b)); return d;
}
__device__ __forceinline__ ull add2(ull a, ull b) {
    ull d; asm("add.rn.f32x2 %0,%1,%2;" : "=l"(d) : "l"(a), "l"(b)); return d;
}
__device__ __forceinline__ ull packdup(float x) {
    ull d; asm("mov.b64 %0,{%1,%1};" : "=l"(d) : "f"(x)); return d;
}
__device__ __forceinline__ float2 unpack2(ull a) {
    float2 v; asm("mov.b64 {%0,%1},%2;" : "=f"(v.x), "=f"(v.y) : "l"(a)); return v;
}
__device__ __forceinline__ unsigned packbf(float a, float b) {
    __nv_bfloat16 ba = __float2bfloat16_rn(a), bb = __float2bfloat16_rn(b);
    return (unsigned)__bfloat16_as_ushort(ba) |
           ((unsigned)__bfloat16_as_ushort(bb) << 16);
}
__device__ __forceinline__ void mma16816(float* c, unsigned a0, unsigned a1,
                                         unsigned a2, unsigned a3,
                                         unsigned b0, unsigned b1) {
    asm("mma.sync.aligned.m16n8k16.row.col.f32.bf16.bf16.f32 "
        "{%0,%1,%2,%3},{%4,%5,%6,%7},{%8,%9},{%0,%1,%2,%3};"
        : "+f"(c[0]), "+f"(c[1]), "+f"(c[2]), "+f"(c[3])
        : "r"(a0), "r"(a1), "r"(a2), "r"(a3), "r"(b0), "r"(b1));
}

// ---- device scratch (zero-initialized at module load) ----
__device__ int   g_cnt[N_MAX];
__device__ int   g_off[N_MAX + 1];
__device__ int   g_perm[E_MAX];
__device__ int   g_zjs[E_MAX];
__device__ int   g_flag;
__device__ float g_ZS[256 * 64];
__device__ float g_ZD[256 * 64];
__device__ float g_meta[(size_t)(E_MAX + 128) * 12];   // SORTED order
__device__ uint4 g_Wb[24 * 4 * 32];                    // bf16 hi/lo B fragments
__device__ float g_S[(size_t)(E_MAX + 128) * 192];     // SORTED order
__device__ float g_accI[N_MAX * 64];
__device__ float g_accA[N_MAX * 64 * 3];
__device__ float g_accS[N_MAX * 64 * 6];

// ------------------------------------------------------------------
// Launch 1: ZS/ZD tables + bf16 W fragment prep + histogram count
// ------------------------------------------------------------------
__global__ void k_pc(const int* __restrict__ ei,
                     const float* __restrict__ emb, const float* __restrict__ e2w,
                     const float* __restrict__ e2b,
                     const float* __restrict__ d1w, const float* __restrict__ d2w,
                     const float* __restrict__ d3w,
                     int nE, int maxz, int Bpre)
{
    int blk = blockIdx.x, tid = threadIdx.x;
    if (blk < Bpre) {
        __shared__ float er[256];
        int zz = blk * 4 + (tid >> 6);
        int h = tid & 63;
        if (zz < maxz) er[(tid >> 6) * 64 + h] = emb[zz * 64 + h];
        __syncthreads();
        if (zz < maxz) {
            const float* e = er + (tid >> 6) * 64;
            float ss = e2b[h], sd = 0.f;
            #pragma unroll 8
            for (int j = 0; j < 64; j++) {
                ss = fmaf(e2w[h * 128 + j], e[j], ss);
                sd = fmaf(e2w[h * 128 + 64 + j], e[j], sd);
            }
            g_ZS[zz * 64 + h] = ss;
            g_ZD[zz * 64 + h] = sd;
        }
    } else if (blk < Bpre + 12) {
        int i = (blk - Bpre) * 256 + tid;
        int lane = i & 31, kk = (i >> 5) & 3, ntg = i >> 7;
        int g = lane >> 2, c = lane & 3;
        int m = ntg * 8 + g;
        const float* W = (m < 64) ? d1w : (m < 128) ? d2w : d3w;
        int h = m & 63;
        int k0 = kk * 16 + 2 * c;
        float w00 = W[h * 64 + k0],     w01 = W[h * 64 + k0 + 1];
        float w10 = W[h * 64 + k0 + 8], w11 = W[h * 64 + k0 + 9];
        __nv_bfloat16 h00 = __float2bfloat16_rn(w00), h01 = __float2bfloat16_rn(w01);
        __nv_bfloat16 h10 = __float2bfloat16_rn(w10), h11 = __float2bfloat16_rn(w11);
        unsigned bh0 = (unsigned)__bfloat16_as_ushort(h00) |
                       ((unsigned)__bfloat16_as_ushort(h01) << 16);
        unsigned bh1 = (unsigned)__bfloat16_as_ushort(h10) |
                       ((unsigned)__bfloat16_as_ushort(h11) << 16);
        unsigned bl0 = packbf(w00 - __bfloat162float(h00), w01 - __bfloat162float(h01));
        unsigned bl1 = packbf(w10 - __bfloat162float(h10), w11 - __bfloat162float(h11));
        g_Wb[i] = make_uint4(bh0, bh1, bl0, bl1);
    } else {
        int e = (blk - Bpre - 12) * 256 + tid;
        if (e < nE) atomicAdd(&g_cnt[ei[e]], 1);
    }
}

// ------------------------------------------------------------------
// Launch 2: fused scan (block 0) + scatter (all blocks, flag-gated)
// ------------------------------------------------------------------
__global__ __launch_bounds__(1024)
void k_ss(const int* __restrict__ ei, const int* __restrict__ z, int nE, int n)
{
    int tid = threadIdx.x, lane = tid & 31, wid = tid >> 5;

    if (blockIdx.x == 0) {
        __shared__ int wsum[32];
        const int CH = 16;
        int beg = tid * CH;
        int loc[CH];
        int s = 0;
        if (beg + CH <= n) {
            int4 a0 = *(const int4*)&g_cnt[beg];
            int4 a1 = *(const int4*)&g_cnt[beg + 4];
            int4 a2 = *(const int4*)&g_cnt[beg + 8];
            int4 a3 = *(const int4*)&g_cnt[beg + 12];
            int v[CH] = {a0.x,a0.y,a0.z,a0.w, a1.x,a1.y,a1.z,a1.w,
                         a2.x,a2.y,a2.z,a2.w, a3.x,a3.y,a3.z,a3.w};
            #pragma unroll
            for (int i = 0; i < CH; i++) { loc[i] = s; s += v[i]; }
        } else {
            #pragma unroll
            for (int i = 0; i < CH; i++) {
                loc[i] = s;
                int idx = beg + i;
                if (idx < n) s += g_cnt[idx];
            }
        }
        int inc = s;
        #pragma unroll
        for (int o = 1; o < 32; o <<= 1) {
            int t = __shfl_up_sync(0xffffffffu, inc, o);
            if (lane >= o) inc += t;
        }
        if (lane == 31) wsum[wid] = inc;
        __syncthreads();
        if (wid == 0) {
            int v = wsum[lane];
            #pragma unroll
            for (int o = 1; o < 32; o <<= 1) {
                int t = __shfl_up_sync(0xffffffffu, v, o);
                if (lane >= o) v += t;
            }
            wsum[lane] = v;
        }
        __syncthreads();
        int excl = inc - s + (wid ? wsum[wid - 1] : 0);
        #pragma unroll
        for (int i = 0; i < CH; i++) {
            int idx = beg + i;
            if (idx < n) { g_off[idx] = excl + loc[i]; g_cnt[idx] = 0; }
        }
        if (tid == 1023) g_off[n] = wsum[31];
        __syncthreads();
        __threadfence();
        if (tid == 0) atomicExch(&g_flag, 1);
    }

    if (tid == 0) {
        while (atomicAdd(&g_flag, 0) == 0) { }
    }
    __syncthreads();

    int e = blockIdx.x * 1024 + tid;
    if (e < nE) {
        int s = ei[e];
        int pos = g_off[s] + atomicAdd(&g_cnt[s], 1);
        g_perm[pos] = e;
        g_zjs[pos] = z[ei[nE + e]];
    }
}

// ------------------------------------------------------------------
// Launch 3: bf16 hi/lo GEMM, SORTED order (R13 shape: M=32/warp)
// ------------------------------------------------------------------
__global__ __launch_bounds__(128)
void k_gemm(const float* __restrict__ attr, const float* __restrict__ ew,
            const float* __restrict__ evn, int nE)
{
    extern __shared__ unsigned smu[];
    unsigned* aHi = smu;
    unsigned* aLo = smu + 128 * 36;

    int tid = threadIdx.x;
    int sBase = blockIdx.x * 128;

    {
        int s = sBase + tid;
        if (s < nE) {
            int e = g_perm[s];
            float w = ew[e];
            float C = (w < RC_F) ? 0.5f * (cosf(w * (PI_F / RC_F)) + 1.0f) : 0.0f;
            float vx = evn[3 * e + 0], vy = evn[3 * e + 1], vz = evn[3 * e + 2];
            float tr3 = (vx * vx + vy * vy + vz * vz) * (1.0f / 3.0f);
            float4* mp = (float4*)(g_meta + (size_t)s * 12);
            mp[0] = make_float4(C, vx, vy, vz);
            mp[1] = make_float4(vx * vx - tr3, vy * vy - tr3, vz * vz - tr3, vx * vy);
            mp[2] = make_float4(vx * vz, vy * vz, 0.f, 0.f);
        }
    }

    {
        int r = tid;
        int srow = sBase + r; if (srow >= nE) srow = nE - 1;
        int e = g_perm[srow];
        const float4* src = (const float4*)(attr + (size_t)e * 64);
        #pragma unroll
        for (int k = 0; k < 16; k++) {
            float4 v = src[k];
            int half = k >> 3, q = k & 7;
            unsigned* dh = aHi + r * 36 + half * 16 + 2 * q;
            unsigned* dl = aLo + r * 36 + half * 16 + 2 * q;
            __nv_bfloat16 hx = __float2bfloat16_rn(v.x), hy = __float2bfloat16_rn(v.y);
            __nv_bfloat16 hz = __float2bfloat16_rn(v.z), hw = __float2bfloat16_rn(v.w);
            dh[0] = (unsigned)__bfloat16_as_ushort(hx) |
                    ((unsigned)__bfloat16_as_ushort(hy) << 16);
            dh[1] = (unsigned)__bfloat16_as_ushort(hz) |
                    ((unsigned)__bfloat16_as_ushort(hw) << 16);
            dl[0] = packbf(v.x - __bfloat162float(hx), v.y - __bfloat162float(hy));
            dl[1] = packbf(v.z - __bfloat162float(hz), v.w - __bfloat162float(hw));
        }
    }
    __syncthreads();

    int warp = tid >> 5, lane = tid & 31;
    int g = lane >> 2, cc = lane & 3;
    int row0 = warp * 32 + g;
    int row1 = row0 + 16;
    size_t eRow0 = (size_t)sBase + row0;

    unsigned AH0[4][4], AL0[4][4], AH1[4][4], AL1[4][4];
    #pragma unroll
    for (int kk = 0; kk < 4; kk++) {
        int base = kk * 8 + cc;
        AH0[kk][0] = aHi[row0 * 36 + base];
        AH0[kk][1] = aHi[(row0 + 8) * 36 + base];
        AH0[kk][2] = aHi[row0 * 36 + base + 4];
        AH0[kk][3] = aHi[(row0 + 8) * 36 + base + 4];
        AL0[kk][0] = aLo[row0 * 36 + base];
        AL0[kk][1] = aLo[(row0 + 8) * 36 + base];
        AL0[kk][2] = aLo[row0 * 36 + base + 4];
        AL0[kk][3] = aLo[(row0 + 8) * 36 + base + 4];
        AH1[kk][0] = aHi[row1 * 36 + base];
        AH1[kk][1] = aHi[(row1 + 8) * 36 + base];
        AH1[kk][2] = aHi[row1 * 36 + base + 4];
        AH1[kk][3] = aHi[(row1 + 8) * 36 + base + 4];
        AL1[kk][0] = aLo[row1 * 36 + base];
        AL1[kk][1] = aLo[(row1 + 8) * 36 + base];
        AL1[kk][2] = aLo[row1 * 36 + base + 4];
        AL1[kk][3] = aLo[(row1 + 8) * 36 + base + 4];
    }

    for (int ntg = 0; ntg < 24; ntg++) {
        float c0[4] = {0.f, 0.f, 0.f, 0.f};
        float c1[4] = {0.f, 0.f, 0.f, 0.f};
        #pragma unroll
        for (int kk = 0; kk < 4; kk++) {
            uint4 bb = __ldg(&g_Wb[(ntg * 4 + kk) * 32 + lane]);
            mma16816(c0, AH0[kk][0], AH0[kk][1], AH0[kk][2], AH0[kk][3], bb.x, bb.y);
            mma16816(c1, AH1[kk][0], AH1[kk][1], AH1[kk][2], AH1[kk][3], bb.x, bb.y);
            mma16816(c0, AH0[kk][0], AH0[kk][1], AH0[kk][2], AH0[kk][3], bb.z, bb.w);
            mma16816(c1, AH1[kk][0], AH1[kk][1], AH1[kk][2], AH1[kk][3], bb.z, bb.w);
            mma16816(c0, AL0[kk][0], AL0[kk][1], AL0[kk][2], AL0[kk][3], bb.x, bb.y);
            mma16816(c1, AL1[kk][0], AL1[kk][1], AL1[kk][2], AL1[kk][3], bb.x, bb.y);
        }
        int m = ntg * 8 + 2 * cc;
        *(float2*)&g_S[eRow0 * 192 + m]        = make_float2(c0[0], c0[1]);
        *(float2*)&g_S[(eRow0 + 8) * 192 + m]  = make_float2(c0[2], c0[3]);
        *(float2*)&g_S[(eRow0 + 16) * 192 + m] = make_float2(c1[0], c1[1]);
        *(float2*)&g_S[(eRow0 + 24) * 192 + m] = make_float2(c1[2], c1[3]);
    }
}

// ------------------------------------------------------------------
// Launch 4 (ncu target): HIGH-OCCUPANCY reduce. Zero smem, minimal
// registers, 1 warp per atom (grid covers all atoms). Per-edge loop.
// ------------------------------------------------------------------
struct Acc { ull I, Ax, Ay, Az, Sxx, Syy, Szz, Sxy, Sxz, Syz; };

__global__ __launch_bounds__(256)
void k_reduce(const int* __restrict__ z,
              const float* __restrict__ d1b, const float* __restrict__ d2b,
              const float* __restrict__ d3b, int n)
{
    int warp = threadIdx.x >> 5, lane = threadIdx.x & 31;
    int atom = blockIdx.x * 8 + warp;
    if (atom >= n) return;

    ull bias1 = ((const ull*)d1b)[lane];
    ull bias2 = ((const ull*)d2b)[lane];
    ull bias3 = ((const ull*)d3b)[lane];

    int e0 = g_off[atom], e1 = g_off[atom + 1];
    Acc A = {0ull,0ull,0ull,0ull,0ull,0ull,0ull,0ull,0ull,0ull};

    if (e0 < e1) {
        ull zS2 = ((const ull*)g_ZS)[z[atom] * 32 + lane];
        int zjn = __ldg(g_zjs + e0);
        for (int s = e0; s < e1; s++) {
            ull zd = __ldg(((const ull*)g_ZD) + zjn * 32 + lane);
            const ull* sp = (const ull*)(g_S + (size_t)s * 192);
            ull s1 = __ldg(sp + lane);
            ull s2 = __ldg(sp + 32 + lane);
            ull s3 = __ldg(sp + 64 + lane);
            const float4* mp = (const float4*)(g_meta + (size_t)s * 12);
            float4 mA = __ldg(mp);
            float4 mB = __ldg(mp + 1);
            float2 mC = __ldg((const float2*)(mp + 2));
            if (s + 1 < e1) zjn = __ldg(g_zjs + s + 1);

            ull zfac = mul2(packdup(mA.x), add2(zS2, zd));
            ull g1 = mul2(add2(s1, bias1), zfac);
            ull g2 = mul2(add2(s2, bias2), zfac);
            ull g3 = mul2(add2(s3, bias3), zfac);
            A.I   = add2(A.I, g1);
            A.Ax  = fma2(g2, packdup(mA.y), A.Ax);
            A.Ay  = fma2(g2, packdup(mA.z), A.Ay);
            A.Az  = fma2(g2, packdup(mA.w), A.Az);
            A.Sxx = fma2(g3, packdup(mB.x), A.Sxx);
            A.Syy = fma2(g3, packdup(mB.y), A.Syy);
            A.Szz = fma2(g3, packdup(mB.z), A.Szz);
            A.Sxy = fma2(g3, packdup(mB.w), A.Sxy);
            A.Sxz = fma2(g3, packdup(mC.x), A.Sxz);
            A.Syz = fma2(g3, packdup(mC.y), A.Syz);
        }
    }

    int base = atom * 64 + lane * 2;
    float2 vI = unpack2(A.I);
    g_accI[base] = vI.x; g_accI[base + 1] = vI.y;
    float2 vAx = unpack2(A.Ax), vAy = unpack2(A.Ay), vAz = unpack2(A.Az);
    int bA = base * 3;
    g_accA[bA + 0] = vAx.x; g_accA[bA + 1] = vAy.x; g_accA[bA + 2] = vAz.x;
    g_accA[bA + 3] = vAx.y; g_accA[bA + 4] = vAy.y; g_accA[bA + 5] = vAz.y;
    float2 vSxx = unpack2(A.Sxx), vSyy = unpack2(A.Syy), vSzz = unpack2(A.Szz);
    float2 vSxy = unpack2(A.Sxy), vSxz = unpack2(A.Sxz), vSyz = unpack2(A.Syz);
    int bS = base * 6;
    g_accS[bS + 0] = vSxx.x; g_accS[bS + 1] = vSyy.x; g_accS[bS + 2] = vSzz.x;
    g_accS[bS + 3] = vSxy.x; g_accS[bS + 4] = vSxz.x; g_accS[bS + 5] = vSyz.x;
    g_accS[bS + 6] = vSxx.y; g_accS[bS + 7] = vSyy.y; g_accS[bS + 8] = vSzz.y;
    g_accS[bS + 9] = vSxy.y; g_accS[bS + 10] = vSxz.y; g_accS[bS + 11] = vSyz.y;
}

// ------------------------------------------------------------------
// Launch 5: tn -> LN -> MLP -> n0 -> diagonal output + cnt/flag re-zero
// ------------------------------------------------------------------
__device__ __forceinline__ float sq(float x) { return x * x; }
__device__ __forceinline__ float silu(float x) { return x / (1.0f + expf(-x)); }

__global__ void k_post(const float* __restrict__ lng, const float* __restrict__ lnb,
                       const float* __restrict__ w1, const float* __restrict__ b1,
                       const float* __restrict__ w2, const float* __restrict__ b2,
                       const float* __restrict__ m0, const float* __restrict__ m1,
                       const float* __restrict__ m2, float* __restrict__ out, int n)
{
    extern __shared__ float sm[];
    float* w1T  = sm;
    float* w2nT = w1T + 64 * 128;
    float* m0T  = w2nT + 128 * 64;
    float* msT  = m0T + 64 * 64;
    float* sb1  = msT + 64 * 64;
    float* sb2  = sb1 + 128;
    float* slg  = sb2 + 64;
    float* slb  = slg + 64;
    float* wk   = slb + 64;

    int tid = threadIdx.x;
    for (int i = tid; i < 64 * 128; i += blockDim.x) {
        int j = i >> 7, o = i & 127;
        w1T[i] = w1[o * 64 + j];
    }
    for (int i = tid; i < 128 * 64; i += blockDim.x) {
        int j = i >> 6, h = i & 63;
        w2nT[i] = w2[h * 3 * 128 + j];
    }
    for (int i = tid; i < 64 * 64; i += blockDim.x) {
        int h = i >> 6, k = i & 63;
        m0T[i] = m0[k * 64 + h];
        msT[i] = m1[k * 64 + h] + m2[k * 64 + h];
    }
    for (int i = tid; i < 128; i += blockDim.x) sb1[i] = b1[i];
    for (int i = tid; i < 64; i += blockDim.x) {
        sb2[i] = b2[3 * i]; slg[i] = lng[i]; slb[i] = lnb[i];
    }
    __syncthreads();

    int warp = tid >> 5, lane = tid & 31;
    float* nm  = wk + warp * 320;
    float* h1  = nm + 64;
    float* wkv = h1 + 128;
    const float2* w2n2 = (const float2*)w2nT;
    const float2* m0v  = (const float2*)m0T;
    const float2* msv  = (const float2*)msT;

    for (int atom = blockIdx.x * NW + warp; atom < n; atom += gridDim.x * NW) {
        int h0 = lane * 2;
        int base = atom * 64 + h0;
        float i0a = g_accI[base], i0b = g_accI[base + 1];
        const float* Ap = g_accA + base * 3;
        const float* Sp = g_accS + base * 6;
        float tna = sq(i0a + Sp[0]) + sq(i0a + Sp[1]) + sq(i0a + Sp[2])
                  + 2.0f * (sq(Sp[3]) + sq(Sp[4]) + sq(Sp[5]) + sq(Ap[0]) + sq(Ap[1]) + sq(Ap[2]));
        float tnb = sq(i0b + Sp[6]) + sq(i0b + Sp[7]) + sq(i0b + Sp[8])
                  + 2.0f * (sq(Sp[9]) + sq(Sp[10]) + sq(Sp[11]) + sq(Ap[3]) + sq(Ap[4]) + sq(Ap[5]));
        wkv[h0] = i0a; wkv[h0 + 1] = i0b;

        float s = tna + tnb;
        for (int o = 16; o; o >>= 1) s += __shfl_xor_sync(0xffffffffu, s, o);
        float mu = s * (1.0f / 64.0f);
        float da = tna - mu, db = tnb - mu;
        float vs = da * da + db * db;
        for (int o = 16; o; o >>= 1) vs += __shfl_xor_sync(0xffffffffu, vs, o);
        float inv = rsqrtf(vs * (1.0f / 64.0f) + 1e-5f);
        nm[h0]     = da * inv * slg[h0] + slb[h0];
        nm[h0 + 1] = db * inv * slg[h0 + 1] + slb[h0 + 1];
        __syncwarp();

        #pragma unroll
        for (int p = 0; p < 4; p++) {
            int o = lane + 32 * p;
            float acc = sb1[o];
            #pragma unroll 8
            for (int j = 0; j < 64; j++) acc = fmaf(w1T[j * 128 + o], nm[j], acc);
            h1[o] = silu(acc);
        }
        __syncwarp();

        float2 acc2 = ((const float2*)sb2)[lane];
        #pragma unroll 8
        for (int j = 0; j < 128; j++) {
            float hv = h1[j];
            float2 wv = w2n2[j * 32 + lane];
            acc2.x = fmaf(wv.x, hv, acc2.x);
            acc2.y = fmaf(wv.y, hv, acc2.y);
        }
        float n0x = silu(acc2.x), n0y = silu(acc2.y);

        float2 d1 = {0.f, 0.f};
        #pragma unroll 8
        for (int h = 0; h < 64; h++) {
            float a = wkv[h];
            float2 m = m0v[h * 32 + lane];
            d1.x = fmaf(m.x, a, d1.x);
            d1.y = fmaf(m.y, a, d1.y);
        }
        d1.x *= n0x; d1.y *= n0y;
        __syncwarp();
        wkv[h0] = d1.x; wkv[h0 + 1] = d1.y;
        __syncwarp();

        float2 tt = {0.f, 0.f};
        #pragma unroll 8
        for (int h = 0; h < 64; h++) {
            float d = wkv[h];
            float2 m = msv[h * 32 + lane];
            tt.x = fmaf(m.x, d, tt.x);
            tt.y = fmaf(m.y, d, tt.y);
        }
        float vx = d1.x + n0x * tt.x;
        float vy = d1.y + n0y * tt.y;

        float2* o = (float2*)(out + (size_t)(atom * 64 + h0) * 9);
        o[0] = make_float2(vx, 0.f);
        o[1] = make_float2(0.f, 0.f);
        o[2] = make_float2(vx, 0.f);
        o[3] = make_float2(0.f, 0.f);
        o[4] = make_float2(vx, vy);
        o[5] = make_float2(0.f, 0.f);
        o[6] = make_float2(0.f, vy);
        o[7] = make_float2(0.f, 0.f);
        o[8] = make_float2(0.f, vy);
        __syncwarp();
    }

    // re-zero g_cnt and g_flag for the next replay
    int gt = blockIdx.x * blockDim.x + threadIdx.x;
    int tot = gridDim.x * blockDim.x;
    for (int i = gt; i < n; i += tot) g_cnt[i] = 0;
    if (gt == 0) g_flag = 0;
}

// ------------------------------------------------------------------
extern "C" void kernel_launch(void* const* d_in, const int* in_sizes, int n_in,
                              void* d_out, int out_size)
{
    const int*   z    = (const int*)d_in[0];
    const int*   ei   = (const int*)d_in[1];
    const float* ew   = (const float*)d_in[2];
    const float* evn  = (const float*)d_in[3];
    const float* attr = (const float*)d_in[4];
    const float* emb  = (const float*)d_in[5];
    const float* e2w  = (const float*)d_in[6];
    const float* e2b  = (const float*)d_in[7];
    const float* d1w  = (const float*)d_in[8];
    const float* d1b  = (const float*)d_in[9];
    const float* d2w  = (const float*)d_in[10];
    const float* d2b  = (const float*)d_in[11];
    const float* d3w  = (const float*)d_in[12];
    const float* d3b  = (const float*)d_in[13];
    const float* lng  = (const float*)d_in[14];
    const float* lnb  = (const float*)d_in[15];
    const float* w1   = (const float*)d_in[16];
    const float* b1   = (const float*)d_in[17];
    const float* w2   = (const float*)d_in[18];
    const float* b2   = (const float*)d_in[19];
    const float* m0   = (const float*)d_in[20];
    const float* m1   = (const float*)d_in[21];
    const float* m2   = (const float*)d_in[22];
    float* out = (float*)d_out;

    int n    = in_sizes[0];
    int nE   = in_sizes[2];
    int maxz = in_sizes[5] / 64;
    if (maxz > 256) maxz = 256;

    int Bpre = (maxz + 3) / 4;
    int Bcnt = (nE + 255) / 256;
    int Bss  = (nE + 1023) / 1024;

    size_t smemG = (size_t)(2 * 128 * 36) * sizeof(unsigned);   // 36864 B
    size_t smemP = (size_t)(64 * 128 + 128 * 64 + 2 * 64 * 64 + 128 + 3 * 64 + NW * 320)
                   * sizeof(float);                              // ~110 KB
    cudaFuncSetAttribute(k_gemm, cudaFuncAttributeMaxDynamicSharedMemorySize, (int)smemG);
    cudaFuncSetAttribute(k_post, cudaFuncAttributeMaxDynamicSharedMemorySize, (int)smemP);

    k_pc<<<Bpre + 12 + Bcnt, 256>>>(ei, emb, e2w, e2b, d1w, d2w, d3w, nE, maxz, Bpre);
    k_ss<<<Bss, 1024>>>(ei, z, nE, n);
    k_gemm<<<(nE + 127) / 128, 128, smemG>>>(attr, ew, evn, nE);
    k_reduce<<<(n + 7) / 8, 256>>>(z, d1b, d2b, d3b, n);           // launch #4 -> ncu
    k_post<<<304, NW * 32, smemP>>>(lng, lnb, w1, b1, w2, b2, m0, m1, m2, out, n);
}

// round 17
// speedup vs baseline: 1.4830x; 1.0664x over previous
#include <cuda_runtime.h>
#include <cuda_bf16.h>
#include <math.h>

#define N_MAX 10000
#define E_MAX 160000
#define NW 8
#define RC_F 4.5f
#define PI_F 3.14159265358979323846f

typedef unsigned long long ull;

__device__ __forceinline__ ull fma2(ull a, ull b, ull c) {
    ull d; asm("fma.rn.f32x2 %0,%1,%2,%3;" : "=l"(d) : "l"(a), "l"(b), "l"(c)); return d;
}
__device__ __forceinline__ ull mul2(ull a, ull b) {
    ull d; asm("mul.rn.f32x2 %0,%1,%2;" : "=l"(d) : "l"(a), "l"(b)); return d;
}
__device__ __forceinline__ ull add2(ull a, ull b) {
    ull d; asm("add.rn.f32x2 %0,%1,%2;" : "=l"(d) : "l"(a), "l"(b)); return d;
}
__device__ __forceinline__ ull packdup(float x) {
    ull d; asm("mov.b64 %0,{%1,%1};" : "=l"(d) : "f"(x)); return d;
}
__device__ __forceinline__ float2 unpack2(ull a) {
    float2 v; asm("mov.b64 {%0,%1},%2;" : "=f"(v.x), "=f"(v.y) : "l"(a)); return v;
}
__device__ __forceinline__ unsigned packbf(float a, float b) {
    __nv_bfloat16 ba = __float2bfloat16_rn(a), bb = __float2bfloat16_rn(b);
    return (unsigned)__bfloat16_as_ushort(ba) |
           ((unsigned)__bfloat16_as_ushort(bb) << 16);
}
__device__ __forceinline__ void mma16816(float* c, unsigned a0, unsigned a1,
                                         unsigned a2, unsigned a3,
                                         unsigned b0, unsigned b1) {
    asm("mma.sync.aligned.m16n8k16.row.col.f32.bf16.bf16.f32 "
        "{%0,%1,%2,%3},{%4,%5,%6,%7},{%8,%9},{%0,%1,%2,%3};"
        : "+f"(c[0]), "+f"(c[1]), "+f"(c[2]), "+f"(c[3])
        : "r"(a0), "r"(a1), "r"(a2), "r"(a3), "r"(b0), "r"(b1));
}

// ---- device scratch (zero-initialized at module load) ----
__device__ int   g_cnt[N_MAX];
__device__ int   g_off[N_MAX + 1];
__device__ int   g_perm[E_MAX];
__device__ int   g_zjs[E_MAX];
__device__ int   g_flag;
__device__ float g_ZS[256 * 64];
__device__ float g_ZD[256 * 64];
__device__ float g_meta[(size_t)(E_MAX + 128) * 12];   // SORTED order
__device__ uint4 g_Wb[24 * 4 * 32];                    // bf16 hi/lo B fragments
// S re-blocked: [blk(1250)][ntg(24)][row(128)][8] floats
__device__ float g_S[(size_t)1250 * 24576];
__device__ float g_accI[N_MAX * 64];
__device__ float g_accA[N_MAX * 64 * 3];
__device__ float g_accS[N_MAX * 64 * 6];

// ------------------------------------------------------------------
// Launch 1: ZS/ZD tables + bf16 W fragment prep + histogram count
// ------------------------------------------------------------------
__global__ void k_pc(const int* __restrict__ ei,
                     const float* __restrict__ emb, const float* __restrict__ e2w,
                     const float* __restrict__ e2b,
                     const float* __restrict__ d1w, const float* __restrict__ d2w,
                     const float* __restrict__ d3w,
                     int nE, int maxz, int Bpre)
{
    int blk = blockIdx.x, tid = threadIdx.x;
    if (blk < Bpre) {
        __shared__ float er[256];
        int zz = blk * 4 + (tid >> 6);
        int h = tid & 63;
        if (zz < maxz) er[(tid >> 6) * 64 + h] = emb[zz * 64 + h];
        __syncthreads();
        if (zz < maxz) {
            const float* e = er + (tid >> 6) * 64;
            float ss = e2b[h], sd = 0.f;
            #pragma unroll 8
            for (int j = 0; j < 64; j++) {
                ss = fmaf(e2w[h * 128 + j], e[j], ss);
                sd = fmaf(e2w[h * 128 + 64 + j], e[j], sd);
            }
            g_ZS[zz * 64 + h] = ss;
            g_ZD[zz * 64 + h] = sd;
        }
    } else if (blk < Bpre + 12) {
        int i = (blk - Bpre) * 256 + tid;
        int lane = i & 31, kk = (i >> 5) & 3, ntg = i >> 7;
        int g = lane >> 2, c = lane & 3;
        int m = ntg * 8 + g;
        const float* W = (m < 64) ? d1w : (m < 128) ? d2w : d3w;
        int h = m & 63;
        int k0 = kk * 16 + 2 * c;
        float w00 = W[h * 64 + k0],     w01 = W[h * 64 + k0 + 1];
        float w10 = W[h * 64 + k0 + 8], w11 = W[h * 64 + k0 + 9];
        __nv_bfloat16 h00 = __float2bfloat16_rn(w00), h01 = __float2bfloat16_rn(w01);
        __nv_bfloat16 h10 = __float2bfloat16_rn(w10), h11 = __float2bfloat16_rn(w11);
        unsigned bh0 = (unsigned)__bfloat16_as_ushort(h00) |
                       ((unsigned)__bfloat16_as_ushort(h01) << 16);
        unsigned bh1 = (unsigned)__bfloat16_as_ushort(h10) |
                       ((unsigned)__bfloat16_as_ushort(h11) << 16);
        unsigned bl0 = packbf(w00 - __bfloat162float(h00), w01 - __bfloat162float(h01));
        unsigned bl1 = packbf(w10 - __bfloat162float(h10), w11 - __bfloat162float(h11));
        g_Wb[i] = make_uint4(bh0, bh1, bl0, bl1);
    } else {
        int e = (blk - Bpre - 12) * 256 + tid;
        if (e < nE) atomicAdd(&g_cnt[ei[e]], 1);
    }
}

// ------------------------------------------------------------------
// Launch 2: fused scan (block 0) + scatter (all blocks, flag-gated)
// ------------------------------------------------------------------
__global__ __launch_bounds__(1024)
void k_ss(const int* __restrict__ ei, const int* __restrict__ z, int nE, int n)
{
    int tid = threadIdx.x, lane = tid & 31, wid = tid >> 5;

    if (blockIdx.x == 0) {
        __shared__ int wsum[32];
        const int CH = 16;
        int beg = tid * CH;
        int loc[CH];
        int s = 0;
        if (beg + CH <= n) {
            int4 a0 = *(const int4*)&g_cnt[beg];
            int4 a1 = *(const int4*)&g_cnt[beg + 4];
            int4 a2 = *(const int4*)&g_cnt[beg + 8];
            int4 a3 = *(const int4*)&g_cnt[beg + 12];
            int v[CH] = {a0.x,a0.y,a0.z,a0.w, a1.x,a1.y,a1.z,a1.w,
                         a2.x,a2.y,a2.z,a2.w, a3.x,a3.y,a3.z,a3.w};
            #pragma unroll
            for (int i = 0; i < CH; i++) { loc[i] = s; s += v[i]; }
        } else {
            #pragma unroll
            for (int i = 0; i < CH; i++) {
                loc[i] = s;
                int idx = beg + i;
                if (idx < n) s += g_cnt[idx];
            }
        }
        int inc = s;
        #pragma unroll
        for (int o = 1; o < 32; o <<= 1) {
            int t = __shfl_up_sync(0xffffffffu, inc, o);
            if (lane >= o) inc += t;
        }
        if (lane == 31) wsum[wid] = inc;
        __syncthreads();
        if (wid == 0) {
            int v = wsum[lane];
            #pragma unroll
            for (int o = 1; o < 32; o <<= 1) {
                int t = __shfl_up_sync(0xffffffffu, v, o);
                if (lane >= o) v += t;
            }
            wsum[lane] = v;
        }
        __syncthreads();
        int excl = inc - s + (wid ? wsum[wid - 1] : 0);
        #pragma unroll
        for (int i = 0; i < CH; i++) {
            int idx = beg + i;
            if (idx < n) { g_off[idx] = excl + loc[i]; g_cnt[idx] = 0; }
        }
        if (tid == 1023) g_off[n] = wsum[31];
        __syncthreads();
        __threadfence();
        if (tid == 0) atomicExch(&g_flag, 1);
    }

    if (tid == 0) {
        while (atomicAdd(&g_flag, 0) == 0) { }
    }
    __syncthreads();

    int e = blockIdx.x * 1024 + tid;
    if (e < nE) {
        int s = ei[e];
        int pos = g_off[s] + atomicAdd(&g_cnt[s], 1);
        g_perm[pos] = e;
        g_zjs[pos] = z[ei[nE + e]];
    }
}

// ------------------------------------------------------------------
// Launch 3: bf16 hi/lo GEMM (M=32/warp), coalesced blocked-S store,
// Wb staged in smem (overlaid on A-tile region after frag load).
// ------------------------------------------------------------------
__global__ __launch_bounds__(128)
void k_gemm(const float* __restrict__ attr, const float* __restrict__ ew,
            const float* __restrict__ evn, int nE)
{
    extern __shared__ unsigned smu[];        // 49152 B
    unsigned* aHi = smu;                     // 128*36 (first 36,864 B)
    unsigned* aLo = smu + 128 * 36;
    uint4* sWb = (uint4*)smu;                // overlaid after frag load

    int tid = threadIdx.x;
    int sBase = blockIdx.x * 128;

    {
        int s = sBase + tid;
        if (s < nE) {
            int e = g_perm[s];
            float w = ew[e];
            float C = (w < RC_F) ? 0.5f * (cosf(w * (PI_F / RC_F)) + 1.0f) : 0.0f;
            float vx = evn[3 * e + 0], vy = evn[3 * e + 1], vz = evn[3 * e + 2];
            float tr3 = (vx * vx + vy * vy + vz * vz) * (1.0f / 3.0f);
            float4* mp = (float4*)(g_meta + (size_t)s * 12);
            mp[0] = make_float4(C, vx, vy, vz);
            mp[1] = make_float4(vx * vx - tr3, vy * vy - tr3, vz * vz - tr3, vx * vy);
            mp[2] = make_float4(vx * vz, vy * vz, 0.f, 0.f);
        }
    }

    {
        int r = tid;
        int srow = sBase + r; if (srow >= nE) srow = nE - 1;
        int e = g_perm[srow];
        const float4* src = (const float4*)(attr + (size_t)e * 64);
        #pragma unroll
        for (int k = 0; k < 16; k++) {
            float4 v = src[k];
            int half = k >> 3, q = k & 7;
            unsigned* dh = aHi + r * 36 + half * 16 + 2 * q;
            unsigned* dl = aLo + r * 36 + half * 16 + 2 * q;
            __nv_bfloat16 hx = __float2bfloat16_rn(v.x), hy = __float2bfloat16_rn(v.y);
            __nv_bfloat16 hz = __float2bfloat16_rn(v.z), hw = __float2bfloat16_rn(v.w);
            dh[0] = (unsigned)__bfloat16_as_ushort(hx) |
                    ((unsigned)__bfloat16_as_ushort(hy) << 16);
            dh[1] = (unsigned)__bfloat16_as_ushort(hz) |
                    ((unsigned)__bfloat16_as_ushort(hw) << 16);
            dl[0] = packbf(v.x - __bfloat162float(hx), v.y - __bfloat162float(hy));
            dl[1] = packbf(v.z - __bfloat162float(hz), v.w - __bfloat162float(hw));
        }
    }
    __syncthreads();

    int warp = tid >> 5, lane = tid & 31;
    int g = lane >> 2, cc = lane & 3;
    int row0 = warp * 32 + g;
    int row1 = row0 + 16;

    unsigned AH0[4][4], AL0[4][4], AH1[4][4], AL1[4][4];
    #pragma unroll
    for (int kk = 0; kk < 4; kk++) {
        int base = kk * 8 + cc;
        AH0[kk][0] = aHi[row0 * 36 + base];
        AH0[kk][1] = aHi[(row0 + 8) * 36 + base];
        AH0[kk][2] = aHi[row0 * 36 + base + 4];
        AH0[kk][3] = aHi[(row0 + 8) * 36 + base + 4];
        AL0[kk][0] = aLo[row0 * 36 + base];
        AL0[kk][1] = aLo[(row0 + 8) * 36 + base];
        AL0[kk][2] = aLo[row0 * 36 + base + 4];
        AL0[kk][3] = aLo[(row0 + 8) * 36 + base + 4];
        AH1[kk][0] = aHi[row1 * 36 + base];
        AH1[kk][1] = aHi[(row1 + 8) * 36 + base];
        AH1[kk][2] = aHi[row1 * 36 + base + 4];
        AH1[kk][3] = aHi[(row1 + 8) * 36 + base + 4];
        AL1[kk][0] = aLo[row1 * 36 + base];
        AL1[kk][1] = aLo[(row1 + 8) * 36 + base];
        AL1[kk][2] = aLo[row1 * 36 + base + 4];
        AL1[kk][3] = aLo[(row1 + 8) * 36 + base + 4];
    }
    __syncthreads();   // A tiles consumed; overlay Wb

    #pragma unroll
    for (int i = 0; i < 24; i++) sWb[i * 128 + tid] = g_Wb[i * 128 + tid];
    __syncthreads();

    float* sOut = g_S + (size_t)blockIdx.x * 24576;
    for (int ntg = 0; ntg < 24; ntg++) {
        float c0[4] = {0.f, 0.f, 0.f, 0.f};
        float c1[4] = {0.f, 0.f, 0.f, 0.f};
        #pragma unroll
        for (int kk = 0; kk < 4; kk++) {
            uint4 bb = sWb[(ntg * 4 + kk) * 32 + lane];
            mma16816(c0, AH0[kk][0], AH0[kk][1], AH0[kk][2], AH0[kk][3], bb.x, bb.y);
            mma16816(c1, AH1[kk][0], AH1[kk][1], AH1[kk][2], AH1[kk][3], bb.x, bb.y);
            mma16816(c0, AH0[kk][0], AH0[kk][1], AH0[kk][2], AH0[kk][3], bb.z, bb.w);
            mma16816(c1, AH1[kk][0], AH1[kk][1], AH1[kk][2], AH1[kk][3], bb.z, bb.w);
            mma16816(c0, AL0[kk][0], AL0[kk][1], AL0[kk][2], AL0[kk][3], bb.x, bb.y);
            mma16816(c1, AL1[kk][0], AL1[kk][1], AL1[kk][2], AL1[kk][3], bb.x, bb.y);
        }
        // blocked layout: [ntg][row][8]; warp writes 8x32B contiguous rows
        float* ob = sOut + ntg * 1024;
        *(float2*)&ob[row0 * 8 + 2 * cc]        = make_float2(c0[0], c0[1]);
        *(float2*)&ob[(row0 + 8) * 8 + 2 * cc]  = make_float2(c0[2], c0[3]);
        *(float2*)&ob[(row0 + 16) * 8 + 2 * cc] = make_float2(c1[0], c1[1]);
        *(float2*)&ob[(row0 + 24) * 8 + 2 * cc] = make_float2(c1[2], c1[3]);
    }
}

// ------------------------------------------------------------------
// Launch 4 (ncu target): high-occupancy reduce, blocked-S reads.
// ------------------------------------------------------------------
struct Acc { ull I, Ax, Ay, Az, Sxx, Syy, Szz, Sxy, Sxz, Syz; };

__global__ __launch_bounds__(256)
void k_reduce(const int* __restrict__ z,
              const float* __restrict__ d1b, const float* __restrict__ d2b,
              const float* __restrict__ d3b, int n)
{
    int warp = threadIdx.x >> 5, lane = threadIdx.x & 31;
    int atom = blockIdx.x * 8 + warp;
    if (atom >= n) return;

    ull bias1 = ((const ull*)d1b)[lane];
    ull bias2 = ((const ull*)d2b)[lane];
    ull bias3 = ((const ull*)d3b)[lane];

    int nt  = lane >> 2;                 // ntg sub-block for this lane's h-pair
    int col = (2 * lane) & 7;

    int e0 = g_off[atom], e1 = g_off[atom + 1];
    Acc A = {0ull,0ull,0ull,0ull,0ull,0ull,0ull,0ull,0ull,0ull};

    if (e0 < e1) {
        ull zS2 = ((const ull*)g_ZS)[z[atom] * 32 + lane];
        int zjn = __ldg(g_zjs + e0);
        for (int s = e0; s < e1; s++) {
            ull zd = __ldg(((const ull*)g_ZD) + zjn * 32 + lane);
            const float* sb = g_S + (size_t)(s >> 7) * 24576 + (s & 127) * 8;
            ull s1 = __ldg((const ull*)(sb + nt * 1024 + col));
            ull s2 = __ldg((const ull*)(sb + (8 + nt) * 1024 + col));
            ull s3 = __ldg((const ull*)(sb + (16 + nt) * 1024 + col));
            const float4* mp = (const float4*)(g_meta + (size_t)s * 12);
            float4 mA = __ldg(mp);
            float4 mB = __ldg(mp + 1);
            float2 mC = __ldg((const float2*)(mp + 2));
            if (s + 1 < e1) zjn = __ldg(g_zjs + s + 1);

            ull zfac = mul2(packdup(mA.x), add2(zS2, zd));
            ull g1 = mul2(add2(s1, bias1), zfac);
            ull g2 = mul2(add2(s2, bias2), zfac);
            ull g3 = mul2(add2(s3, bias3), zfac);
            A.I   = add2(A.I, g1);
            A.Ax  = fma2(g2, packdup(mA.y), A.Ax);
            A.Ay  = fma2(g2, packdup(mA.z), A.Ay);
            A.Az  = fma2(g2, packdup(mA.w), A.Az);
            A.Sxx = fma2(g3, packdup(mB.x), A.Sxx);
            A.Syy = fma2(g3, packdup(mB.y), A.Syy);
            A.Szz = fma2(g3, packdup(mB.z), A.Szz);
            A.Sxy = fma2(g3, packdup(mB.w), A.Sxy);
            A.Sxz = fma2(g3, packdup(mC.x), A.Sxz);
            A.Syz = fma2(g3, packdup(mC.y), A.Syz);
        }
    }

    int base = atom * 64 + lane * 2;
    float2 vI = unpack2(A.I);
    g_accI[base] = vI.x; g_accI[base + 1] = vI.y;
    float2 vAx = unpack2(A.Ax), vAy = unpack2(A.Ay), vAz = unpack2(A.Az);
    int bA = base * 3;
    g_accA[bA + 0] = vAx.x; g_accA[bA + 1] = vAy.x; g_accA[bA + 2] = vAz.x;
    g_accA[bA + 3] = vAx.y; g_accA[bA + 4] = vAy.y; g_accA[bA + 5] = vAz.y;
    float2 vSxx = unpack2(A.Sxx), vSyy = unpack2(A.Syy), vSzz = unpack2(A.Szz);
    float2 vSxy = unpack2(A.Sxy), vSxz = unpack2(A.Sxz), vSyz = unpack2(A.Syz);
    int bS = base * 6;
    g_accS[bS + 0] = vSxx.x; g_accS[bS + 1] = vSyy.x; g_accS[bS + 2] = vSzz.x;
    g_accS[bS + 3] = vSxy.x; g_accS[bS + 4] = vSxz.x; g_accS[bS + 5] = vSyz.x;
    g_accS[bS + 6] = vSxx.y; g_accS[bS + 7] = vSyy.y; g_accS[bS + 8] = vSzz.y;
    g_accS[bS + 9] = vSxy.y; g_accS[bS + 10] = vSxz.y; g_accS[bS + 11] = vSyz.y;
}

// ------------------------------------------------------------------
// Launch 5: tn -> LN -> MLP -> n0 -> diagonal output + cnt/flag re-zero
// ------------------------------------------------------------------
__device__ __forceinline__ float sq(float x) { return x * x; }
__device__ __forceinline__ float silu(float x) { return x / (1.0f + expf(-x)); }

__global__ void k_post(const float* __restrict__ lng, const float* __restrict__ lnb,
                       const float* __restrict__ w1, const float* __restrict__ b1,
                       const float* __restrict__ w2, const float* __restrict__ b2,
                       const float* __restrict__ m0, const float* __restrict__ m1,
                       const float* __restrict__ m2, float* __restrict__ out, int n)
{
    extern __shared__ float sm[];
    float* w1T  = sm;
    float* w2nT = w1T + 64 * 128;
    float* m0T  = w2nT + 128 * 64;
    float* msT  = m0T + 64 * 64;
    float* sb1  = msT + 64 * 64;
    float* sb2  = sb1 + 128;
    float* slg  = sb2 + 64;
    float* slb  = slg + 64;
    float* wk   = slb + 64;

    int tid = threadIdx.x;
    for (int i = tid; i < 64 * 128; i += blockDim.x) {
        int j = i >> 7, o = i & 127;
        w1T[i] = w1[o * 64 + j];
    }
    for (int i = tid; i < 128 * 64; i += blockDim.x) {
        int j = i >> 6, h = i & 63;
        w2nT[i] = w2[h * 3 * 128 + j];
    }
    for (int i = tid; i < 64 * 64; i += blockDim.x) {
        int h = i >> 6, k = i & 63;
        m0T[i] = m0[k * 64 + h];
        msT[i] = m1[k * 64 + h] + m2[k * 64 + h];
    }
    for (int i = tid; i < 128; i += blockDim.x) sb1[i] = b1[i];
    for (int i = tid; i < 64; i += blockDim.x) {
        sb2[i] = b2[3 * i]; slg[i] = lng[i]; slb[i] = lnb[i];
    }
    __syncthreads();

    int warp = tid >> 5, lane = tid & 31;
    float* nm  = wk + warp * 320;
    float* h1  = nm + 64;
    float* wkv = h1 + 128;
    const float2* w2n2 = (const float2*)w2nT;
    const float2* m0v  = (const float2*)m0T;
    const float2* msv  = (const float2*)msT;

    for (int atom = blockIdx.x * NW + warp; atom < n; atom += gridDim.x * NW) {
        int h0 = lane * 2;
        int base = atom * 64 + h0;
        float i0a = g_accI[base], i0b = g_accI[base + 1];
        const float* Ap = g_accA + base * 3;
        const float* Sp = g_accS + base * 6;
        float tna = sq(i0a + Sp[0]) + sq(i0a + Sp[1]) + sq(i0a + Sp[2])
                  + 2.0f * (sq(Sp[3]) + sq(Sp[4]) + sq(Sp[5]) + sq(Ap[0]) + sq(Ap[1]) + sq(Ap[2]));
        float tnb = sq(i0b + Sp[6]) + sq(i0b + Sp[7]) + sq(i0b + Sp[8])
                  + 2.0f * (sq(Sp[9]) + sq(Sp[10]) + sq(Sp[11]) + sq(Ap[3]) + sq(Ap[4]) + sq(Ap[5]));
        wkv[h0] = i0a; wkv[h0 + 1] = i0b;

        float s = tna + tnb;
        for (int o = 16; o; o >>= 1) s += __shfl_xor_sync(0xffffffffu, s, o);
        float mu = s * (1.0f / 64.0f);
        float da = tna - mu, db = tnb - mu;
        float vs = da * da + db * db;
        for (int o = 16; o; o >>= 1) vs += __shfl_xor_sync(0xffffffffu, vs, o);
        float inv = rsqrtf(vs * (1.0f / 64.0f) + 1e-5f);
        nm[h0]     = da * inv * slg[h0] + slb[h0];
        nm[h0 + 1] = db * inv * slg[h0 + 1] + slb[h0 + 1];
        __syncwarp();

        #pragma unroll
        for (int p = 0; p < 4; p++) {
            int o = lane + 32 * p;
            float acc = sb1[o];
            #pragma unroll 8
            for (int j = 0; j < 64; j++) acc = fmaf(w1T[j * 128 + o], nm[j], acc);
            h1[o] = silu(acc);
        }
        __syncwarp();

        float2 acc2 = ((const float2*)sb2)[lane];
        #pragma unroll 8
        for (int j = 0; j < 128; j++) {
            float hv = h1[j];
            float2 wv = w2n2[j * 32 + lane];
            acc2.x = fmaf(wv.x, hv, acc2.x);
            acc2.y = fmaf(wv.y, hv, acc2.y);
        }
        float n0x = silu(acc2.x), n0y = silu(acc2.y);

        float2 d1 = {0.f, 0.f};
        #pragma unroll 8
        for (int h = 0; h < 64; h++) {
            float a = wkv[h];
            float2 m = m0v[h * 32 + lane];
            d1.x = fmaf(m.x, a, d1.x);
            d1.y = fmaf(m.y, a, d1.y);
        }
        d1.x *= n0x; d1.y *= n0y;
        __syncwarp();
        wkv[h0] = d1.x; wkv[h0 + 1] = d1.y;
        __syncwarp();

        float2 tt = {0.f, 0.f};
        #pragma unroll 8
        for (int h = 0; h < 64; h++) {
            float d = wkv[h];
            float2 m = msv[h * 32 + lane];
            tt.x = fmaf(m.x, d, tt.x);
            tt.y = fmaf(m.y, d, tt.y);
        }
        float vx = d1.x + n0x * tt.x;
        float vy = d1.y + n0y * tt.y;

        float2* o = (float2*)(out + (size_t)(atom * 64 + h0) * 9);
        o[0] = make_float2(vx, 0.f);
        o[1] = make_float2(0.f, 0.f);
        o[2] = make_float2(vx, 0.f);
        o[3] = make_float2(0.f, 0.f);
        o[4] = make_float2(vx, vy);
        o[5] = make_float2(0.f, 0.f);
        o[6] = make_float2(0.f, vy);
        o[7] = make_float2(0.f, 0.f);
        o[8] = make_float2(0.f, vy);
        __syncwarp();
    }

    // re-zero g_cnt and g_flag for the next replay
    int gt = blockIdx.x * blockDim.x + threadIdx.x;
    int tot = gridDim.x * blockDim.x;
    for (int i = gt; i < n; i += tot) g_cnt[i] = 0;
    if (gt == 0) g_flag = 0;
}

// ------------------------------------------------------------------
extern "C" void kernel_launch(void* const* d_in, const int* in_sizes, int n_in,
                              void* d_out, int out_size)
{
    const int*   z    = (const int*)d_in[0];
    const int*   ei   = (const int*)d_in[1];
    const float* ew   = (const float*)d_in[2];
    const float* evn  = (const float*)d_in[3];
    const float* attr = (const float*)d_in[4];
    const float* emb  = (const float*)d_in[5];
    const float* e2w  = (const float*)d_in[6];
    const float* e2b  = (const float*)d_in[7];
    const float* d1w  = (const float*)d_in[8];
    const float* d1b  = (const float*)d_in[9];
    const float* d2w  = (const float*)d_in[10];
    const float* d2b  = (const float*)d_in[11];
    const float* d3w  = (const float*)d_in[12];
    const float* d3b  = (const float*)d_in[13];
    const float* lng  = (const float*)d_in[14];
    const float* lnb  = (const float*)d_in[15];
    const float* w1   = (const float*)d_in[16];
    const float* b1   = (const float*)d_in[17];
    const float* w2   = (const float*)d_in[18];
    const float* b2   = (const float*)d_in[19];
    const float* m0   = (const float*)d_in[20];
    const float* m1   = (const float*)d_in[21];
    const float* m2   = (const float*)d_in[22];
    float* out = (float*)d_out;

    int n    = in_sizes[0];
    int nE   = in_sizes[2];
    int maxz = in_sizes[5] / 64;
    if (maxz > 256) maxz = 256;

    int Bpre = (maxz + 3) / 4;
    int Bcnt = (nE + 255) / 256;
    int Bss  = (nE + 1023) / 1024;

    size_t smemG = 49152;
    size_t smemP = (size_t)(64 * 128 + 128 * 64 + 2 * 64 * 64 + 128 + 3 * 64 + NW * 320)
                   * sizeof(float);
    cudaFuncSetAttribute(k_gemm, cudaFuncAttributeMaxDynamicSharedMemorySize, (int)smemG);
    cudaFuncSetAttribute(k_post, cudaFuncAttributeMaxDynamicSharedMemorySize, (int)smemP);

    k_pc<<<Bpre + 12 + Bcnt, 256>>>(ei, emb, e2w, e2b, d1w, d2w, d3w, nE, maxz, Bpre);
    k_ss<<<Bss, 1024>>>(ei, z, nE, n);
    k_gemm<<<(nE + 127) / 128, 128, smemG>>>(attr, ew, evn, nE);
    k_reduce<<<(n + 7) / 8, 256>>>(z, d1b, d2b, d3b, n);           // launch #4 -> ncu
    k_post<<<304, NW * 32, smemP>>>(lng, lnb, w1, b1, w2, b2, m0, m1, m2, out, n);
}